// round 13
// baseline (speedup 1.0000x reference)
#include <cuda_runtime.h>
#include <cuda_fp16.h>
#include <math.h>
#include <stdint.h>

// ---------------------------------------------------------------------------
// Problem constants
// ---------------------------------------------------------------------------
#define BATCH 2
#define CH    256
#define L     32768
#define NH    8
#define TOTW  1024
#define MROWS 65536

// ---------------------------------------------------------------------------
// Scratch (device globals; allocation-free)
// ---------------------------------------------------------------------------
__device__ float  g_h[(size_t)BATCH * L * CH];      // residual stream fp32 [b][p][c]
__device__ __half g_win[(size_t)MROWS * CH];        // fp16 activations (GEMM A)
__device__ __half g_qkv[(size_t)MROWS * 768];       // fp16 qkv; also fp32-view scratch
__device__ __half g_mid[(size_t)MROWS * 1024];      // fp16 MLP hidden
__device__ __half g_wts[3145728];                   // fp16 weights, [N][K]
__device__ __half g_pwT[CH * CH];                   // fp16 pointwise W [co][ci]=[N][K]
__device__ float  g_tab[8 * 8 * 64 * 64];           // attn bias+mask table

#define W_QKV 0
#define W_PROJ 786432
#define W_FC1 1048576
#define W_FC2 2097152

// ---------------------------------------------------------------------------
// Batched 2D transpose (fp32, for harness I/O layout)
// ---------------------------------------------------------------------------
__global__ void transpose_k(const float* __restrict__ in, float* __restrict__ out,
                            int R, int Cc) {
    __shared__ float tile[32][33];
    int b  = blockIdx.z;
    int r0 = blockIdx.x * 32, c0 = blockIdx.y * 32;
    const float* ib = in  + (size_t)b * R * Cc;
    float*       ob = out + (size_t)b * R * Cc;
    int tx = threadIdx.x, ty = threadIdx.y;
#pragma unroll
    for (int i = 0; i < 4; i++)
        tile[ty + i * 8][tx] = ib[(size_t)(r0 + ty + i * 8) * Cc + c0 + tx];
    __syncthreads();
#pragma unroll
    for (int i = 0; i < 4; i++)
        ob[(size_t)(c0 + ty + i * 8) * R + r0 + tx] = tile[tx][ty + i * 8];
}

// Transpose + fp16-convert weights: [R][C] -> [C][R], batched over z
__global__ void wtransH_k(const float* __restrict__ in, __half* __restrict__ out,
                          int R, int Cc) {
    __shared__ float tile[32][33];
    int b  = blockIdx.z;
    int r0 = blockIdx.x * 32, c0 = blockIdx.y * 32;
    const float* ib = in  + (size_t)b * R * Cc;
    __half*      ob = out + (size_t)b * R * Cc;
    int tx = threadIdx.x, ty = threadIdx.y;
#pragma unroll
    for (int i = 0; i < 4; i++)
        tile[ty + i * 8][tx] = ib[(size_t)(r0 + ty + i * 8) * Cc + c0 + tx];
    __syncthreads();
#pragma unroll
    for (int i = 0; i < 4; i++)
        ob[(size_t)(c0 + ty + i * 8) * R + r0 + tx] = __float2half_rn(tile[tx][ty + i * 8]);
}

// Convert only (fp32 -> fp16)
__global__ void cvt_k(const float* __restrict__ src, __half* __restrict__ dst, int n) {
    int i = blockIdx.x * 256 + threadIdx.x;
    if (i < n) dst[i] = __float2half_rn(src[i]);
}

// ---------------------------------------------------------------------------
// Window-token index -> source row (fused roll)
// ---------------------------------------------------------------------------
__device__ __forceinline__ int decomp_win(int wt_idx, int shift) {
    int widx = wt_idx >> 6, n = wt_idx & 63;
    int b = widx >> 9;  int wr = widx & 511;
    int wh = wr >> 6, ww = (wr >> 3) & 7, wt = wr & 7;
    int i = n >> 4, j = (n >> 2) & 3, k = n & 3;
    int gh = (wh * 4 + i + shift) & 31;
    int gw = (ww * 4 + j + shift) & 31;
    int gt = (wt * 4 + k + shift) & 31;
    return b * L + gh * 1024 + gw * 32 + gt;
}

// Block-wide sum of (v, v*v) with warp shuffles; one barrier.
__device__ __forceinline__ void blk_stats(float v, int tid, float& mean, float& var) {
    float s1 = v, s2 = v * v;
#pragma unroll
    for (int o = 16; o > 0; o >>= 1) {
        s1 += __shfl_xor_sync(0xFFFFFFFFu, s1, o);
        s2 += __shfl_xor_sync(0xFFFFFFFFu, s2, o);
    }
    __shared__ float ws1[8], ws2[8];
    if ((tid & 31) == 0) { ws1[tid >> 5] = s1; ws2[tid >> 5] = s2; }
    __syncthreads();
    float t1 = 0.f, t2 = 0.f;
#pragma unroll
    for (int w = 0; w < 8; w++) { t1 += ws1[w]; t2 += ws2[w]; }
    mean = t1 * (1.f / 256.f);
    var  = t2 * (1.f / 256.f) - mean * mean;
}

// LN + roll + window-partition; output fp16
__global__ void ln_winpart_k(const float* __restrict__ h, const float* __restrict__ g,
                             const float* __restrict__ be, __half* __restrict__ out,
                             int shift) {
    int srow = decomp_win(blockIdx.x, shift);
    int tid = threadIdx.x;
    float v = h[(size_t)srow * CH + tid];
    float mean, var;
    blk_stats(v, tid, mean, var);
    out[(size_t)blockIdx.x * CH + tid] =
        __float2half_rn((v - mean) * rsqrtf(var + 1e-5f) * g[tid] + be[tid]);
}

// Window reverse + residual add + LN2 fused; LN out (token order) fp16
__global__ void winrev_ln_k(const float* __restrict__ p, float* __restrict__ h,
                            const float* __restrict__ g, const float* __restrict__ be,
                            __half* __restrict__ out, int shift) {
    int srow = decomp_win(blockIdx.x, shift);
    int tid = threadIdx.x;
    float v = h[(size_t)srow * CH + tid] + p[(size_t)blockIdx.x * CH + tid];
    h[(size_t)srow * CH + tid] = v;
    float mean, var;
    blk_stats(v, tid, mean, var);
    out[(size_t)srow * CH + tid] =
        __float2half_rn((v - mean) * rsqrtf(var + 1e-5f) * g[tid] + be[tid]);
}

// ---------------------------------------------------------------------------
// Attention bias+mask table
// ---------------------------------------------------------------------------
__device__ __forceinline__ int axlab(int border, int i) {
    return border ? (i >= 2 ? 2 : 1) : 0;
}

__global__ void attn_tab_k(const float* __restrict__ rpb, float* __restrict__ tab,
                           int shift) {
    int cls = blockIdx.x >> 3, head = blockIdx.x & 7;
    int r = threadIdx.x;
    int bh = (cls >> 2) & 1, bw = (cls >> 1) & 1, bt = cls & 1;
    int ri = r >> 4, rj = (r >> 2) & 3, rk = r & 3;
    int labr = axlab(bh, ri) * 9 + axlab(bw, rj) * 3 + axlab(bt, rk);
    float* dst = tab + ((size_t)(cls * 8 + head) * 64 + r) * 64;
    for (int m = 0; m < 64; m++) {
        int mi = m >> 4, mj = (m >> 2) & 3, mk = m & 3;
        float v = rpb[((ri - mi + 3) * 49 + (rj - mj + 3) * 7 + (rk - mk + 3)) * 8 + head];
        if (shift) {
            int labm = axlab(bh, mi) * 9 + axlab(bw, mj) * 3 + axlab(bt, mk);
            if (labm != labr) v -= 100.f;
        }
        dst[m] = v;
    }
}

// ---------------------------------------------------------------------------
// Tensor-core windowed attention: one WARP per (window, head).
// ---------------------------------------------------------------------------
__device__ __forceinline__ void mma16816a(float* d, uint32_t a0, uint32_t a1,
                                          uint32_t a2, uint32_t a3,
                                          uint32_t b0, uint32_t b1) {
    asm volatile(
        "mma.sync.aligned.m16n8k16.row.col.f32.f16.f16.f32 "
        "{%0,%1,%2,%3},{%4,%5,%6,%7},{%8,%9},{%0,%1,%2,%3};"
        : "+f"(d[0]), "+f"(d[1]), "+f"(d[2]), "+f"(d[3])
        : "r"(a0), "r"(a1), "r"(a2), "r"(a3), "r"(b0), "r"(b1));
}
__device__ __forceinline__ uint32_t h2u(__half2 h) { return *(uint32_t*)&h; }

__global__ __launch_bounds__(128)
void attn_k(const __half* __restrict__ qkv, const float* __restrict__ tab,
            __half* __restrict__ o, int shift) {
    int widx = blockIdx.x >> 1;
    int head = (blockIdx.x & 1) * 4 + (threadIdx.x >> 5);
    int lane = threadIdx.x & 31;
    int g = lane >> 2, cc = lane & 3;

    const __half* base = qkv + (size_t)widx * 64 * 768;
    const __half* Q = base + head * 32;
    const __half* K = base + 256 + head * 32;
    const __half* V = base + 512 + head * 32;

    int cls = 0;
    if (shift) {
        int wr = widx & 511;
        cls = (((wr >> 6) == 7) << 2) | ((((wr >> 3) & 7) == 7) << 1) | ((wr & 7) == 7);
    }
    const float* T = tab + (size_t)(cls * 8 + head) * 4096;

    // ---- S = Q K^T  (64x64x32) ----
    float S[4][8][4];
#pragma unroll
    for (int i = 0; i < 4; i++)
#pragma unroll
        for (int j = 0; j < 8; j++)
#pragma unroll
            for (int c = 0; c < 4; c++) S[i][j][c] = 0.f;

#pragma unroll
    for (int t = 0; t < 2; t++) {
        uint32_t a[4][4];
#pragma unroll
        for (int i = 0; i < 4; i++) {
            const __half* q0 = Q + (size_t)(16 * i + g) * 768 + t * 16 + 2 * cc;
            a[i][0] = *(const uint32_t*)(q0);
            a[i][1] = *(const uint32_t*)(q0 + 8 * 768);
            a[i][2] = *(const uint32_t*)(q0 + 8);
            a[i][3] = *(const uint32_t*)(q0 + 8 * 768 + 8);
        }
        uint32_t bq[8][2];
#pragma unroll
        for (int j = 0; j < 8; j++) {
            const __half* k0 = K + (size_t)(8 * j + g) * 768 + t * 16 + 2 * cc;
            bq[j][0] = *(const uint32_t*)(k0);
            bq[j][1] = *(const uint32_t*)(k0 + 8);
        }
#pragma unroll
        for (int i = 0; i < 4; i++)
#pragma unroll
            for (int j = 0; j < 8; j++)
                mma16816a(S[i][j], a[i][0], a[i][1], a[i][2], a[i][3],
                          bq[j][0], bq[j][1]);
    }

    // ---- scale + bias ----
    const float sc = 0.17677669529663687f;
#pragma unroll
    for (int i = 0; i < 4; i++)
#pragma unroll
        for (int j = 0; j < 8; j++) {
            float2 t0 = *(const float2*)&T[(16 * i + g) * 64 + 8 * j + 2 * cc];
            float2 t1 = *(const float2*)&T[(16 * i + g + 8) * 64 + 8 * j + 2 * cc];
            S[i][j][0] = S[i][j][0] * sc + t0.x;
            S[i][j][1] = S[i][j][1] * sc + t0.y;
            S[i][j][2] = S[i][j][2] * sc + t1.x;
            S[i][j][3] = S[i][j][3] * sc + t1.y;
        }

    // ---- softmax ----
    float inv0[4], inv1[4];
#pragma unroll
    for (int i = 0; i < 4; i++) {
        float m0 = -1e30f, m1 = -1e30f;
#pragma unroll
        for (int j = 0; j < 8; j++) {
            m0 = fmaxf(m0, fmaxf(S[i][j][0], S[i][j][1]));
            m1 = fmaxf(m1, fmaxf(S[i][j][2], S[i][j][3]));
        }
        m0 = fmaxf(m0, __shfl_xor_sync(0xFFFFFFFFu, m0, 1));
        m0 = fmaxf(m0, __shfl_xor_sync(0xFFFFFFFFu, m0, 2));
        m1 = fmaxf(m1, __shfl_xor_sync(0xFFFFFFFFu, m1, 1));
        m1 = fmaxf(m1, __shfl_xor_sync(0xFFFFFFFFu, m1, 2));
        float s0 = 0.f, s1 = 0.f;
#pragma unroll
        for (int j = 0; j < 8; j++) {
            float e0 = __expf(S[i][j][0] - m0);
            float e1 = __expf(S[i][j][1] - m0);
            float e2 = __expf(S[i][j][2] - m1);
            float e3 = __expf(S[i][j][3] - m1);
            S[i][j][0] = e0; S[i][j][1] = e1; S[i][j][2] = e2; S[i][j][3] = e3;
            s0 += e0 + e1; s1 += e2 + e3;
        }
        s0 += __shfl_xor_sync(0xFFFFFFFFu, s0, 1);
        s0 += __shfl_xor_sync(0xFFFFFFFFu, s0, 2);
        s1 += __shfl_xor_sync(0xFFFFFFFFu, s1, 1);
        s1 += __shfl_xor_sync(0xFFFFFFFFu, s1, 2);
        inv0[i] = 1.f / s0;
        inv1[i] = 1.f / s1;
    }

    // ---- scores -> fp16 A fragments ----
    uint32_t Sh[4][8][2];
#pragma unroll
    for (int i = 0; i < 4; i++)
#pragma unroll
        for (int j = 0; j < 8; j++) {
            Sh[i][j][0] = h2u(__floats2half2_rn(S[i][j][0], S[i][j][1]));
            Sh[i][j][1] = h2u(__floats2half2_rn(S[i][j][2], S[i][j][3]));
        }

    // ---- O = S V  (64x32x64) ----
    float O[4][4][4];
#pragma unroll
    for (int i = 0; i < 4; i++)
#pragma unroll
        for (int j = 0; j < 4; j++)
#pragma unroll
            for (int c = 0; c < 4; c++) O[i][j][c] = 0.f;

#pragma unroll
    for (int t = 0; t < 4; t++) {
        uint32_t bv[4][2];
#pragma unroll
        for (int j = 0; j < 4; j++) {
            const __half* v0 = V + (size_t)(16 * t + 2 * cc) * 768 + 8 * j + g;
            bv[j][0] = h2u(__halves2half2(v0[0], v0[768]));
            bv[j][1] = h2u(__halves2half2(v0[8 * 768], v0[9 * 768]));
        }
#pragma unroll
        for (int i = 0; i < 4; i++)
#pragma unroll
            for (int j = 0; j < 4; j++)
                mma16816a(O[i][j], Sh[i][2 * t][0], Sh[i][2 * t][1],
                          Sh[i][2 * t + 1][0], Sh[i][2 * t + 1][1],
                          bv[j][0], bv[j][1]);
    }

    // ---- write out ----
    __half* ob = o + (size_t)widx * 64 * CH + head * 32;
#pragma unroll
    for (int i = 0; i < 4; i++) {
        int r0 = 16 * i + g;
#pragma unroll
        for (int j = 0; j < 4; j++) {
            int col = 8 * j + 2 * cc;
            *(__half2*)(ob + (size_t)r0 * CH + col) =
                __floats2half2_rn(O[i][j][0] * inv0[i], O[i][j][1] * inv0[i]);
            *(__half2*)(ob + (size_t)(r0 + 8) * CH + col) =
                __floats2half2_rn(O[i][j][2] * inv1[i], O[i][j][3] * inv1[i]);
        }
    }
}

// ---------------------------------------------------------------------------
// FP16 tensor-core GEMM: mma.sync.m16n8k16, ldmatrix fragments.
// Block tile 128x128, 8 warps (2x4), warp tile 64x32.
// K-tile 64 halves (128B rows + 16B pad, RSTR=72) -> HALF the barriers of
// the 32-half version. cp.async TWO-stage, issue-next-before-wait schedule.
// 2 CTAs/SM (smem 72KB x2 = 144KB <= 228KB, opt-in via FuncSetAttribute).
// EPI: 0 bias, 1 bias+GELU, 2 bias+residual, 3 bias+ReLU. OHALF: fp16 out.
// ---------------------------------------------------------------------------
#define RSTR 72                           // halves per smem row (64 data + 8 pad)
#define ASTAGE (128 * RSTR)               // halves
#define BSTAGE (128 * RSTR)
#define HG_SMEM ((2 * ASTAGE + 2 * BSTAGE) * 2)   // 73728 bytes

__device__ __forceinline__ uint32_t smem_u32(const void* p) {
    uint32_t a;
    asm("{ .reg .u64 t; cvta.to.shared.u64 t, %1; cvt.u32.u64 %0, t; }" : "=r"(a) : "l"(p));
    return a;
}
__device__ __forceinline__ void cp16(uint32_t dst, const void* src) {
    asm volatile("cp.async.cg.shared.global [%0], [%1], 16;\n" :: "r"(dst), "l"(src));
}
__device__ __forceinline__ void ldm4(uint32_t* f, uint32_t a) {
    asm volatile("ldmatrix.sync.aligned.m8n8.x4.shared.b16 {%0,%1,%2,%3}, [%4];"
                 : "=r"(f[0]), "=r"(f[1]), "=r"(f[2]), "=r"(f[3]) : "r"(a));
}
__device__ __forceinline__ void mma16816(float* d, const uint32_t* a, uint32_t b0, uint32_t b1) {
    asm volatile(
        "mma.sync.aligned.m16n8k16.row.col.f32.f16.f16.f32 "
        "{%0,%1,%2,%3},{%4,%5,%6,%7},{%8,%9},{%0,%1,%2,%3};"
        : "+f"(d[0]), "+f"(d[1]), "+f"(d[2]), "+f"(d[3])
        : "r"(a[0]), "r"(a[1]), "r"(a[2]), "r"(a[3]), "r"(b0), "r"(b1));
}

template <int EPI, int OHALF>
__global__ __launch_bounds__(256, 2)
void hgemm_k(const __half* __restrict__ A, const __half* __restrict__ Bw,
             const float* __restrict__ bias, const float* __restrict__ res,
             float* __restrict__ C, __half* __restrict__ C16, int M, int N, int K) {
    extern __shared__ __half sh[];
    uint32_t sA[2], sB[2];
    sA[0] = smem_u32(sh);
    sA[1] = sA[0] + ASTAGE * 2;
    sB[0] = sA[1] + ASTAGE * 2;
    sB[1] = sB[0] + BSTAGE * 2;

    int tid = threadIdx.x, lane = tid & 31, warp = tid >> 5;
    int wm = (warp & 1) * 64, wn = (warp >> 1) * 32;
    int bm = blockIdx.y * 128, bn = blockIdx.x * 128;

    uint32_t aoff = (uint32_t)(lane & 15) * (RSTR * 2) + ((lane >> 4) & 1) * 16;
    uint32_t boff = (uint32_t)((lane & 7) + ((lane >> 4) & 1) * 8) * (RSTR * 2)
                  + ((lane >> 3) & 1) * 16;

    // loader: row = tid>>1 (0..127), half = tid&1; 64 bytes (4x cp16) each
    int arow = tid >> 1, ahalf = tid & 1;
    const __half* Ag = A + (size_t)(bm + arow) * K + ahalf * 32;
    const __half* Bg = Bw + (size_t)(bn + arow) * K + ahalf * 32;
    uint32_t adst = (uint32_t)arow * (RSTR * 2) + (uint32_t)ahalf * 64;

    float acc[4][4][4];
#pragma unroll
    for (int i = 0; i < 4; i++)
#pragma unroll
        for (int j = 0; j < 4; j++)
#pragma unroll
            for (int c2 = 0; c2 < 4; c2++) acc[i][j][c2] = 0.f;

    int nkt = K >> 6;

#pragma unroll
    for (int i = 0; i < 4; i++) {
        cp16(sA[0] + adst + i * 16, Ag + i * 8);
        cp16(sB[0] + adst + i * 16, Bg + i * 8);
    }
    asm volatile("cp.async.commit_group;\n");

    int buf = 0;
    for (int kt = 0; kt < nkt; kt++) {
        if (kt + 1 < nkt) {
            int ko = (kt + 1) * 64;
            uint32_t da = sA[buf ^ 1], db = sB[buf ^ 1];
#pragma unroll
            for (int i = 0; i < 4; i++) {
                cp16(da + adst + i * 16, Ag + ko + i * 8);
                cp16(db + adst + i * 16, Bg + ko + i * 8);
            }
            asm volatile("cp.async.commit_group;\n");
            asm volatile("cp.async.wait_group 1;\n");
        } else {
            asm volatile("cp.async.wait_group 0;\n");
        }
        __syncthreads();

        uint32_t sa = sA[buf], sbb = sB[buf];
#pragma unroll
        for (int kk = 0; kk < 4; kk++) {
            uint32_t af[4][4], bf[2][4];
#pragma unroll
            for (int im = 0; im < 4; im++)
                ldm4(af[im], sa + (uint32_t)(wm + im * 16) * (RSTR * 2) + kk * 32 + aoff);
#pragma unroll
            for (int jn = 0; jn < 2; jn++)
                ldm4(bf[jn], sbb + (uint32_t)(wn + jn * 16) * (RSTR * 2) + kk * 32 + boff);
#pragma unroll
            for (int im = 0; im < 4; im++)
#pragma unroll
                for (int jn = 0; jn < 2; jn++) {
                    mma16816(acc[im][jn * 2],     af[im], bf[jn][0], bf[jn][1]);
                    mma16816(acc[im][jn * 2 + 1], af[im], bf[jn][2], bf[jn][3]);
                }
        }
        __syncthreads();
        buf ^= 1;
    }

    int g = lane >> 2, cc = lane & 3;
#pragma unroll
    for (int im = 0; im < 4; im++) {
        int row0 = bm + wm + im * 16 + g;
#pragma unroll
        for (int j = 0; j < 4; j++) {
            int col = bn + wn + j * 8 + cc * 2;
            float b0 = bias[col], b1 = bias[col + 1];
            float v0 = acc[im][j][0] + b0, v1 = acc[im][j][1] + b1;
            float v2 = acc[im][j][2] + b0, v3 = acc[im][j][3] + b1;
            if (EPI == 1) {
                v0 = 0.5f * v0 * (1.f + erff(v0 * 0.70710678118654752f));
                v1 = 0.5f * v1 * (1.f + erff(v1 * 0.70710678118654752f));
                v2 = 0.5f * v2 * (1.f + erff(v2 * 0.70710678118654752f));
                v3 = 0.5f * v3 * (1.f + erff(v3 * 0.70710678118654752f));
            }
            if (EPI == 2) {
                float2 r0v = *(const float2*)&res[(size_t)row0 * N + col];
                float2 r1v = *(const float2*)&res[(size_t)(row0 + 8) * N + col];
                v0 += r0v.x; v1 += r0v.y; v2 += r1v.x; v3 += r1v.y;
            }
            if (EPI == 3) {
                v0 = fmaxf(v0, 0.f); v1 = fmaxf(v1, 0.f);
                v2 = fmaxf(v2, 0.f); v3 = fmaxf(v3, 0.f);
            }
            if (OHALF) {
                *(__half2*)&C16[(size_t)row0 * N + col]       = __floats2half2_rn(v0, v1);
                *(__half2*)&C16[(size_t)(row0 + 8) * N + col] = __floats2half2_rn(v2, v3);
            } else {
                float2 o0; o0.x = v0; o0.y = v1;
                float2 o1; o1.x = v2; o1.y = v3;
                *(float2*)&C[(size_t)row0 * N + col] = o0;
                *(float2*)&C[(size_t)(row0 + 8) * N + col] = o1;
            }
        }
    }
}

// ---------------------------------------------------------------------------
// Depthwise 3x3x3 conv, channels-last; fp16 out
// ---------------------------------------------------------------------------
__global__ __launch_bounds__(256)
void dwconv_k(const float* __restrict__ in, const float* __restrict__ w,
              __half* __restrict__ out) {
    __shared__ float ws[256 * 27];
    int tid = threadIdx.x;
    for (int idx = tid; idx < 256 * 27; idx += 256) ws[idx] = w[idx];
    __syncthreads();
    int bx = blockIdx.x;
    int tc = bx & 3;  bx >>= 2;
    int wp = bx & 31; bx >>= 5;
    int hp = bx & 31; bx >>= 5;
    int b  = bx;
    int c  = tid;
    const float* ib = in  + (size_t)b * L * CH;
    __half*      ob = out + (size_t)b * L * CH;
#pragma unroll
    for (int tt = 0; tt < 8; tt++) {
        int t = tc * 8 + tt;
        float acc = 0.f;
#pragma unroll
        for (int dh = -1; dh <= 1; dh++) {
            int h2 = hp + dh; if (h2 < 0 || h2 > 31) continue;
#pragma unroll
            for (int dw = -1; dw <= 1; dw++) {
                int w2 = wp + dw; if (w2 < 0 || w2 > 31) continue;
#pragma unroll
                for (int dt = -1; dt <= 1; dt++) {
                    int t2 = t + dt; if (t2 < 0 || t2 > 31) continue;
                    acc += ws[c * 27 + (dh + 1) * 9 + (dw + 1) * 3 + (dt + 1)] *
                           ib[(size_t)(h2 * 1024 + w2 * 32 + t2) * CH + c];
                }
            }
        }
        ob[(size_t)(hp * 1024 + wp * 32 + t) * CH + c] = __float2half_rn(acc);
    }
}

// ---------------------------------------------------------------------------
// Launch
// ---------------------------------------------------------------------------
extern "C" void kernel_launch(void* const* d_in, const int* in_sizes, int n_in,
                              void* d_out, int out_size) {
    const float* x      = (const float*)d_in[0];
    const float* g1     = (const float*)d_in[1];
    const float* b1     = (const float*)d_in[2];
    const float* qkv_w  = (const float*)d_in[3];
    const float* qkv_b  = (const float*)d_in[4];
    const float* proj_w = (const float*)d_in[5];
    const float* proj_b = (const float*)d_in[6];
    const float* rpb    = (const float*)d_in[7];
    const float* g2     = (const float*)d_in[8];
    const float* b2     = (const float*)d_in[9];
    const float* fc1_w  = (const float*)d_in[10];
    const float* fc1_b  = (const float*)d_in[11];
    const float* fc2_w  = (const float*)d_in[12];
    const float* fc2_b  = (const float*)d_in[13];
    const float* dw_w   = (const float*)d_in[14];
    const float* pw_w   = (const float*)d_in[15];
    const float* pw_b   = (const float*)d_in[16];
    float* out = (float*)d_out;

    float *ph, *ptab;
    __half *hwin, *hqkv, *hmid, *hwts, *hpwT;
    cudaGetSymbolAddress((void**)&ph,   g_h);
    cudaGetSymbolAddress((void**)&hwin, g_win);
    cudaGetSymbolAddress((void**)&hqkv, g_qkv);
    cudaGetSymbolAddress((void**)&hmid, g_mid);
    cudaGetSymbolAddress((void**)&hwts, g_wts);
    cudaGetSymbolAddress((void**)&hpwT, g_pwT);
    cudaGetSymbolAddress((void**)&ptab, g_tab);
    float* fscratch = (float*)hqkv;   // fp32 view for proj/pw outputs

    cudaFuncSetAttribute(hgemm_k<0, 1>, cudaFuncAttributeMaxDynamicSharedMemorySize, HG_SMEM);
    cudaFuncSetAttribute(hgemm_k<0, 0>, cudaFuncAttributeMaxDynamicSharedMemorySize, HG_SMEM);
    cudaFuncSetAttribute(hgemm_k<1, 1>, cudaFuncAttributeMaxDynamicSharedMemorySize, HG_SMEM);
    cudaFuncSetAttribute(hgemm_k<2, 0>, cudaFuncAttributeMaxDynamicSharedMemorySize, HG_SMEM);
    cudaFuncSetAttribute(hgemm_k<3, 0>, cudaFuncAttributeMaxDynamicSharedMemorySize, HG_SMEM);

    // weight prepass: [K][N] -> [N][K] fp16
    wtransH_k<<<dim3(8, 24, 4), dim3(32, 8)>>>(qkv_w,  hwts + W_QKV,  256, 768);
    wtransH_k<<<dim3(8, 8, 4),  dim3(32, 8)>>>(proj_w, hwts + W_PROJ, 256, 256);
    wtransH_k<<<dim3(8, 32, 4), dim3(32, 8)>>>(fc1_w,  hwts + W_FC1,  256, 1024);
    wtransH_k<<<dim3(32, 8, 4), dim3(32, 8)>>>(fc2_w,  hwts + W_FC2,  1024, 256);
    cvt_k<<<256, 256>>>(pw_w, hpwT, 65536);       // [co][ci] already [N][K]

    // x [b][c][p] -> h [b][p][c]
    transpose_k<<<dim3(8, 1024, 2), dim3(32, 8)>>>(x, ph, 256, 32768);

    for (int blk = 0; blk < 4; blk++) {
        int shift = (blk & 1) ? 2 : 0;
        ln_winpart_k<<<MROWS, 256>>>(ph, g1 + blk * 256, b1 + blk * 256, hwin, shift);
        hgemm_k<0, 1><<<dim3(6, 512), 256, HG_SMEM>>>(
            hwin, hwts + W_QKV + (size_t)blk * 256 * 768, qkv_b + blk * 768, nullptr,
            nullptr, hqkv, MROWS, 768, 256);
        attn_tab_k<<<64, 64>>>(rpb + blk * 343 * 8, ptab, shift);
        attn_k<<<TOTW * 2, 128>>>(hqkv, ptab, hwin, shift);
        hgemm_k<0, 0><<<dim3(2, 512), 256, HG_SMEM>>>(
            hwin, hwts + W_PROJ + (size_t)blk * 256 * 256, proj_b + blk * 256, nullptr,
            fscratch, nullptr, MROWS, 256, 256);
        winrev_ln_k<<<MROWS, 256>>>(fscratch, ph, g2 + blk * 256, b2 + blk * 256, hwin, shift);
        hgemm_k<1, 1><<<dim3(8, 512), 256, HG_SMEM>>>(
            hwin, hwts + W_FC1 + (size_t)blk * 256 * 1024, fc1_b + blk * 1024, nullptr,
            nullptr, hmid, MROWS, 1024, 256);
        hgemm_k<2, 0><<<dim3(2, 512), 256, HG_SMEM>>>(
            hmid, hwts + W_FC2 + (size_t)blk * 1024 * 256, fc2_b + blk * 256, ph,
            ph, nullptr, MROWS, 256, 1024);
    }

    dwconv_k<<<BATCH * 32 * 32 * 4, 256>>>(ph, dw_w, hwin);
    hgemm_k<3, 0><<<dim3(2, 512), 256, HG_SMEM>>>(
        hwin, hpwT, pw_b, nullptr, fscratch, nullptr, MROWS, 256, 256);
    transpose_k<<<dim3(1024, 8, 2), dim3(32, 8)>>>(fscratch, out, 32768, 256);
}

// round 14
// speedup vs baseline: 1.0547x; 1.0547x over previous
#include <cuda_runtime.h>
#include <cuda_fp16.h>
#include <math.h>
#include <stdint.h>

// ---------------------------------------------------------------------------
// Problem constants
// ---------------------------------------------------------------------------
#define BATCH 2
#define CH    256
#define L     32768
#define NH    8
#define TOTW  1024
#define MROWS 65536

// ---------------------------------------------------------------------------
// Scratch (device globals; allocation-free)
// ---------------------------------------------------------------------------
__device__ float  g_h[(size_t)BATCH * L * CH];      // residual stream fp32 [b][p][c]
__device__ __half g_win[(size_t)MROWS * CH];        // fp16 activations (GEMM A)
__device__ __half g_qkv[(size_t)MROWS * 768];       // fp16 qkv; also fp32-view scratch
__device__ __half g_mid[(size_t)MROWS * 1024];      // fp16 MLP hidden
__device__ __half g_wts[3145728];                   // fp16 weights, [N][K]
__device__ __half g_pwT[CH * CH];                   // fp16 pointwise W [co][ci]=[N][K]
__device__ float  g_tab[8 * 8 * 64 * 64];           // attn bias+mask table

#define W_QKV 0
#define W_PROJ 786432
#define W_FC1 1048576
#define W_FC2 2097152

// ---------------------------------------------------------------------------
// Batched 2D transpose (fp32, for harness I/O layout)
// ---------------------------------------------------------------------------
__global__ void transpose_k(const float* __restrict__ in, float* __restrict__ out,
                            int R, int Cc) {
    __shared__ float tile[32][33];
    int b  = blockIdx.z;
    int r0 = blockIdx.x * 32, c0 = blockIdx.y * 32;
    const float* ib = in  + (size_t)b * R * Cc;
    float*       ob = out + (size_t)b * R * Cc;
    int tx = threadIdx.x, ty = threadIdx.y;
#pragma unroll
    for (int i = 0; i < 4; i++)
        tile[ty + i * 8][tx] = ib[(size_t)(r0 + ty + i * 8) * Cc + c0 + tx];
    __syncthreads();
#pragma unroll
    for (int i = 0; i < 4; i++)
        ob[(size_t)(c0 + ty + i * 8) * R + r0 + tx] = tile[tx][ty + i * 8];
}

// Transpose + fp16-convert weights: [R][C] -> [C][R], batched over z
__global__ void wtransH_k(const float* __restrict__ in, __half* __restrict__ out,
                          int R, int Cc) {
    __shared__ float tile[32][33];
    int b  = blockIdx.z;
    int r0 = blockIdx.x * 32, c0 = blockIdx.y * 32;
    const float* ib = in  + (size_t)b * R * Cc;
    __half*      ob = out + (size_t)b * R * Cc;
    int tx = threadIdx.x, ty = threadIdx.y;
#pragma unroll
    for (int i = 0; i < 4; i++)
        tile[ty + i * 8][tx] = ib[(size_t)(r0 + ty + i * 8) * Cc + c0 + tx];
    __syncthreads();
#pragma unroll
    for (int i = 0; i < 4; i++)
        ob[(size_t)(c0 + ty + i * 8) * R + r0 + tx] = __float2half_rn(tile[tx][ty + i * 8]);
}

// Convert only (fp32 -> fp16)
__global__ void cvt_k(const float* __restrict__ src, __half* __restrict__ dst, int n) {
    int i = blockIdx.x * 256 + threadIdx.x;
    if (i < n) dst[i] = __float2half_rn(src[i]);
}

// ---------------------------------------------------------------------------
// Window-token index -> source row (fused roll)
// ---------------------------------------------------------------------------
__device__ __forceinline__ int decomp_win(int wt_idx, int shift) {
    int widx = wt_idx >> 6, n = wt_idx & 63;
    int b = widx >> 9;  int wr = widx & 511;
    int wh = wr >> 6, ww = (wr >> 3) & 7, wt = wr & 7;
    int i = n >> 4, j = (n >> 2) & 3, k = n & 3;
    int gh = (wh * 4 + i + shift) & 31;
    int gw = (ww * 4 + j + shift) & 31;
    int gt = (wt * 4 + k + shift) & 31;
    return b * L + gh * 1024 + gw * 32 + gt;
}

// Block-wide sum of (v, v*v) with warp shuffles; one barrier.
__device__ __forceinline__ void blk_stats(float v, int tid, float& mean, float& var) {
    float s1 = v, s2 = v * v;
#pragma unroll
    for (int o = 16; o > 0; o >>= 1) {
        s1 += __shfl_xor_sync(0xFFFFFFFFu, s1, o);
        s2 += __shfl_xor_sync(0xFFFFFFFFu, s2, o);
    }
    __shared__ float ws1[8], ws2[8];
    if ((tid & 31) == 0) { ws1[tid >> 5] = s1; ws2[tid >> 5] = s2; }
    __syncthreads();
    float t1 = 0.f, t2 = 0.f;
#pragma unroll
    for (int w = 0; w < 8; w++) { t1 += ws1[w]; t2 += ws2[w]; }
    mean = t1 * (1.f / 256.f);
    var  = t2 * (1.f / 256.f) - mean * mean;
}

// LN + roll + window-partition; output fp16
__global__ void ln_winpart_k(const float* __restrict__ h, const float* __restrict__ g,
                             const float* __restrict__ be, __half* __restrict__ out,
                             int shift) {
    int srow = decomp_win(blockIdx.x, shift);
    int tid = threadIdx.x;
    float v = h[(size_t)srow * CH + tid];
    float mean, var;
    blk_stats(v, tid, mean, var);
    out[(size_t)blockIdx.x * CH + tid] =
        __float2half_rn((v - mean) * rsqrtf(var + 1e-5f) * g[tid] + be[tid]);
}

// Window reverse + residual add + LN2 fused; LN out (token order) fp16
__global__ void winrev_ln_k(const float* __restrict__ p, float* __restrict__ h,
                            const float* __restrict__ g, const float* __restrict__ be,
                            __half* __restrict__ out, int shift) {
    int srow = decomp_win(blockIdx.x, shift);
    int tid = threadIdx.x;
    float v = h[(size_t)srow * CH + tid] + p[(size_t)blockIdx.x * CH + tid];
    h[(size_t)srow * CH + tid] = v;
    float mean, var;
    blk_stats(v, tid, mean, var);
    out[(size_t)srow * CH + tid] =
        __float2half_rn((v - mean) * rsqrtf(var + 1e-5f) * g[tid] + be[tid]);
}

// ---------------------------------------------------------------------------
// Attention bias+mask table
// ---------------------------------------------------------------------------
__device__ __forceinline__ int axlab(int border, int i) {
    return border ? (i >= 2 ? 2 : 1) : 0;
}

__global__ void attn_tab_k(const float* __restrict__ rpb, float* __restrict__ tab,
                           int shift) {
    int cls = blockIdx.x >> 3, head = blockIdx.x & 7;
    int r = threadIdx.x;
    int bh = (cls >> 2) & 1, bw = (cls >> 1) & 1, bt = cls & 1;
    int ri = r >> 4, rj = (r >> 2) & 3, rk = r & 3;
    int labr = axlab(bh, ri) * 9 + axlab(bw, rj) * 3 + axlab(bt, rk);
    float* dst = tab + ((size_t)(cls * 8 + head) * 64 + r) * 64;
    for (int m = 0; m < 64; m++) {
        int mi = m >> 4, mj = (m >> 2) & 3, mk = m & 3;
        float v = rpb[((ri - mi + 3) * 49 + (rj - mj + 3) * 7 + (rk - mk + 3)) * 8 + head];
        if (shift) {
            int labm = axlab(bh, mi) * 9 + axlab(bw, mj) * 3 + axlab(bt, mk);
            if (labm != labr) v -= 100.f;
        }
        dst[m] = v;
    }
}

// ---------------------------------------------------------------------------
// Tensor-core windowed attention: one WARP per (window, head).
// ---------------------------------------------------------------------------
__device__ __forceinline__ void mma16816a(float* d, uint32_t a0, uint32_t a1,
                                          uint32_t a2, uint32_t a3,
                                          uint32_t b0, uint32_t b1) {
    asm volatile(
        "mma.sync.aligned.m16n8k16.row.col.f32.f16.f16.f32 "
        "{%0,%1,%2,%3},{%4,%5,%6,%7},{%8,%9},{%0,%1,%2,%3};"
        : "+f"(d[0]), "+f"(d[1]), "+f"(d[2]), "+f"(d[3])
        : "r"(a0), "r"(a1), "r"(a2), "r"(a3), "r"(b0), "r"(b1));
}
__device__ __forceinline__ uint32_t h2u(__half2 h) { return *(uint32_t*)&h; }

__global__ __launch_bounds__(128)
void attn_k(const __half* __restrict__ qkv, const float* __restrict__ tab,
            __half* __restrict__ o, int shift) {
    int widx = blockIdx.x >> 1;
    int head = (blockIdx.x & 1) * 4 + (threadIdx.x >> 5);
    int lane = threadIdx.x & 31;
    int g = lane >> 2, cc = lane & 3;

    const __half* base = qkv + (size_t)widx * 64 * 768;
    const __half* Q = base + head * 32;
    const __half* K = base + 256 + head * 32;
    const __half* V = base + 512 + head * 32;

    int cls = 0;
    if (shift) {
        int wr = widx & 511;
        cls = (((wr >> 6) == 7) << 2) | ((((wr >> 3) & 7) == 7) << 1) | ((wr & 7) == 7);
    }
    const float* T = tab + (size_t)(cls * 8 + head) * 4096;

    // ---- S = Q K^T  (64x64x32) ----
    float S[4][8][4];
#pragma unroll
    for (int i = 0; i < 4; i++)
#pragma unroll
        for (int j = 0; j < 8; j++)
#pragma unroll
            for (int c = 0; c < 4; c++) S[i][j][c] = 0.f;

#pragma unroll
    for (int t = 0; t < 2; t++) {
        uint32_t a[4][4];
#pragma unroll
        for (int i = 0; i < 4; i++) {
            const __half* q0 = Q + (size_t)(16 * i + g) * 768 + t * 16 + 2 * cc;
            a[i][0] = *(const uint32_t*)(q0);
            a[i][1] = *(const uint32_t*)(q0 + 8 * 768);
            a[i][2] = *(const uint32_t*)(q0 + 8);
            a[i][3] = *(const uint32_t*)(q0 + 8 * 768 + 8);
        }
        uint32_t bq[8][2];
#pragma unroll
        for (int j = 0; j < 8; j++) {
            const __half* k0 = K + (size_t)(8 * j + g) * 768 + t * 16 + 2 * cc;
            bq[j][0] = *(const uint32_t*)(k0);
            bq[j][1] = *(const uint32_t*)(k0 + 8);
        }
#pragma unroll
        for (int i = 0; i < 4; i++)
#pragma unroll
            for (int j = 0; j < 8; j++)
                mma16816a(S[i][j], a[i][0], a[i][1], a[i][2], a[i][3],
                          bq[j][0], bq[j][1]);
    }

    // ---- scale + bias ----
    const float sc = 0.17677669529663687f;
#pragma unroll
    for (int i = 0; i < 4; i++)
#pragma unroll
        for (int j = 0; j < 8; j++) {
            float2 t0 = *(const float2*)&T[(16 * i + g) * 64 + 8 * j + 2 * cc];
            float2 t1 = *(const float2*)&T[(16 * i + g + 8) * 64 + 8 * j + 2 * cc];
            S[i][j][0] = S[i][j][0] * sc + t0.x;
            S[i][j][1] = S[i][j][1] * sc + t0.y;
            S[i][j][2] = S[i][j][2] * sc + t1.x;
            S[i][j][3] = S[i][j][3] * sc + t1.y;
        }

    // ---- softmax ----
    float inv0[4], inv1[4];
#pragma unroll
    for (int i = 0; i < 4; i++) {
        float m0 = -1e30f, m1 = -1e30f;
#pragma unroll
        for (int j = 0; j < 8; j++) {
            m0 = fmaxf(m0, fmaxf(S[i][j][0], S[i][j][1]));
            m1 = fmaxf(m1, fmaxf(S[i][j][2], S[i][j][3]));
        }
        m0 = fmaxf(m0, __shfl_xor_sync(0xFFFFFFFFu, m0, 1));
        m0 = fmaxf(m0, __shfl_xor_sync(0xFFFFFFFFu, m0, 2));
        m1 = fmaxf(m1, __shfl_xor_sync(0xFFFFFFFFu, m1, 1));
        m1 = fmaxf(m1, __shfl_xor_sync(0xFFFFFFFFu, m1, 2));
        float s0 = 0.f, s1 = 0.f;
#pragma unroll
        for (int j = 0; j < 8; j++) {
            float e0 = __expf(S[i][j][0] - m0);
            float e1 = __expf(S[i][j][1] - m0);
            float e2 = __expf(S[i][j][2] - m1);
            float e3 = __expf(S[i][j][3] - m1);
            S[i][j][0] = e0; S[i][j][1] = e1; S[i][j][2] = e2; S[i][j][3] = e3;
            s0 += e0 + e1; s1 += e2 + e3;
        }
        s0 += __shfl_xor_sync(0xFFFFFFFFu, s0, 1);
        s0 += __shfl_xor_sync(0xFFFFFFFFu, s0, 2);
        s1 += __shfl_xor_sync(0xFFFFFFFFu, s1, 1);
        s1 += __shfl_xor_sync(0xFFFFFFFFu, s1, 2);
        inv0[i] = 1.f / s0;
        inv1[i] = 1.f / s1;
    }

    // ---- scores -> fp16 A fragments ----
    uint32_t Sh[4][8][2];
#pragma unroll
    for (int i = 0; i < 4; i++)
#pragma unroll
        for (int j = 0; j < 8; j++) {
            Sh[i][j][0] = h2u(__floats2half2_rn(S[i][j][0], S[i][j][1]));
            Sh[i][j][1] = h2u(__floats2half2_rn(S[i][j][2], S[i][j][3]));
        }

    // ---- O = S V  (64x32x64) ----
    float O[4][4][4];
#pragma unroll
    for (int i = 0; i < 4; i++)
#pragma unroll
        for (int j = 0; j < 4; j++)
#pragma unroll
            for (int c = 0; c < 4; c++) O[i][j][c] = 0.f;

#pragma unroll
    for (int t = 0; t < 4; t++) {
        uint32_t bv[4][2];
#pragma unroll
        for (int j = 0; j < 4; j++) {
            const __half* v0 = V + (size_t)(16 * t + 2 * cc) * 768 + 8 * j + g;
            bv[j][0] = h2u(__halves2half2(v0[0], v0[768]));
            bv[j][1] = h2u(__halves2half2(v0[8 * 768], v0[9 * 768]));
        }
#pragma unroll
        for (int i = 0; i < 4; i++)
#pragma unroll
            for (int j = 0; j < 4; j++)
                mma16816a(O[i][j], Sh[i][2 * t][0], Sh[i][2 * t][1],
                          Sh[i][2 * t + 1][0], Sh[i][2 * t + 1][1],
                          bv[j][0], bv[j][1]);
    }

    // ---- write out ----
    __half* ob = o + (size_t)widx * 64 * CH + head * 32;
#pragma unroll
    for (int i = 0; i < 4; i++) {
        int r0 = 16 * i + g;
#pragma unroll
        for (int j = 0; j < 4; j++) {
            int col = 8 * j + 2 * cc;
            *(__half2*)(ob + (size_t)r0 * CH + col) =
                __floats2half2_rn(O[i][j][0] * inv0[i], O[i][j][1] * inv0[i]);
            *(__half2*)(ob + (size_t)(r0 + 8) * CH + col) =
                __floats2half2_rn(O[i][j][2] * inv1[i], O[i][j][3] * inv1[i]);
        }
    }
}

// ---------------------------------------------------------------------------
// FP16 tensor-core GEMM: mma.sync.m16n8k16, ldmatrix fragments.
// Block tile 128x128, 8 warps (2x4), warp tile 64x32, K-tile 32 halves.
// THREE-stage cp.async ring, ONE barrier per tile, depth-2 prefetch:
//   wait_group 1 -> syncthreads -> issue stage kt+2 -> compute stage kt.
// (Issue at iter kt targets buffer (kt+2)%3 = the one computed at kt-1,
//  which all warps finished before this iter's barrier.)
// 2 CTAs/SM (smem 60KB x2 = 120KB). B=W^T [N][K]; non-trans ldmatrix. RSTR=40.
// EPI: 0 bias, 1 bias+GELU, 2 bias+residual, 3 bias+ReLU. OHALF: fp16 out.
// ---------------------------------------------------------------------------
#define RSTR 40                           // halves per smem row
#define ASTAGE (128 * RSTR)               // halves
#define BSTAGE (128 * RSTR)
#define STG_H (ASTAGE + BSTAGE)           // halves per stage
#define HG_SMEM (3 * STG_H * 2)           // 61440 bytes

__device__ __forceinline__ uint32_t smem_u32(const void* p) {
    uint32_t a;
    asm("{ .reg .u64 t; cvta.to.shared.u64 t, %1; cvt.u32.u64 %0, t; }" : "=r"(a) : "l"(p));
    return a;
}
__device__ __forceinline__ void cp16(uint32_t dst, const void* src) {
    asm volatile("cp.async.cg.shared.global [%0], [%1], 16;\n" :: "r"(dst), "l"(src));
}
__device__ __forceinline__ void ldm4(uint32_t* f, uint32_t a) {
    asm volatile("ldmatrix.sync.aligned.m8n8.x4.shared.b16 {%0,%1,%2,%3}, [%4];"
                 : "=r"(f[0]), "=r"(f[1]), "=r"(f[2]), "=r"(f[3]) : "r"(a));
}
__device__ __forceinline__ void mma16816(float* d, const uint32_t* a, uint32_t b0, uint32_t b1) {
    asm volatile(
        "mma.sync.aligned.m16n8k16.row.col.f32.f16.f16.f32 "
        "{%0,%1,%2,%3},{%4,%5,%6,%7},{%8,%9},{%0,%1,%2,%3};"
        : "+f"(d[0]), "+f"(d[1]), "+f"(d[2]), "+f"(d[3])
        : "r"(a[0]), "r"(a[1]), "r"(a[2]), "r"(a[3]), "r"(b0), "r"(b1));
}

template <int EPI, int OHALF>
__global__ __launch_bounds__(256, 2)
void hgemm_k(const __half* __restrict__ A, const __half* __restrict__ Bw,
             const float* __restrict__ bias, const float* __restrict__ res,
             float* __restrict__ C, __half* __restrict__ C16, int M, int N, int K) {
    extern __shared__ __half sh[];
    uint32_t stA[3], stB[3];
#pragma unroll
    for (int s = 0; s < 3; s++) {
        stA[s] = smem_u32(sh) + (uint32_t)s * (STG_H * 2);
        stB[s] = stA[s] + ASTAGE * 2;
    }

    int tid = threadIdx.x, lane = tid & 31, warp = tid >> 5;
    int wm = (warp & 1) * 64, wn = (warp >> 1) * 32;
    int bm = blockIdx.y * 128, bn = blockIdx.x * 128;

    uint32_t aoff = (uint32_t)(lane & 15) * (RSTR * 2) + ((lane >> 4) & 1) * 16;
    uint32_t boff = (uint32_t)((lane & 7) + ((lane >> 4) & 1) * 8) * (RSTR * 2)
                  + ((lane >> 3) & 1) * 16;

    int arow = tid >> 1, ach = (tid & 1) * 2;
    const __half* Ag = A + (size_t)(bm + arow) * K + ach * 8;
    const __half* Bg = Bw + (size_t)(bn + arow) * K + ach * 8;
    uint32_t adst = (uint32_t)arow * (RSTR * 2) + ach * 16;

    float acc[4][4][4];
#pragma unroll
    for (int i = 0; i < 4; i++)
#pragma unroll
        for (int j = 0; j < 4; j++)
#pragma unroll
            for (int c2 = 0; c2 < 4; c2++) acc[i][j][c2] = 0.f;

    int nkt = K >> 5;

#define HG_ISSUE(sbuf, ko)                                                    \
    do {                                                                      \
        uint32_t da = stA[sbuf], db = stB[sbuf];                              \
        cp16(da + adst,      Ag + (ko));                                      \
        cp16(da + adst + 16, Ag + (ko) + 8);                                  \
        cp16(db + adst,      Bg + (ko));                                      \
        cp16(db + adst + 16, Bg + (ko) + 8);                                  \
        asm volatile("cp.async.commit_group;\n");                             \
    } while (0)

    HG_ISSUE(0, 0);
    HG_ISSUE(1, 32);

    for (int kt = 0; kt < nkt; kt++) {
        if (kt + 1 < nkt)
            asm volatile("cp.async.wait_group 1;\n");
        else
            asm volatile("cp.async.wait_group 0;\n");
        __syncthreads();
        if (kt + 2 < nkt) HG_ISSUE((kt + 2) % 3, (kt + 2) * 32);

        int cb = kt % 3;
        uint32_t sa = stA[cb], sbb = stB[cb];
#pragma unroll
        for (int kk = 0; kk < 2; kk++) {
            uint32_t af[4][4], bf[2][4];
#pragma unroll
            for (int im = 0; im < 4; im++)
                ldm4(af[im], sa + (uint32_t)(wm + im * 16) * (RSTR * 2) + kk * 32 + aoff);
#pragma unroll
            for (int jn = 0; jn < 2; jn++)
                ldm4(bf[jn], sbb + (uint32_t)(wn + jn * 16) * (RSTR * 2) + kk * 32 + boff);
#pragma unroll
            for (int im = 0; im < 4; im++)
#pragma unroll
                for (int jn = 0; jn < 2; jn++) {
                    mma16816(acc[im][jn * 2],     af[im], bf[jn][0], bf[jn][1]);
                    mma16816(acc[im][jn * 2 + 1], af[im], bf[jn][2], bf[jn][3]);
                }
        }
    }
#undef HG_ISSUE

    int g = lane >> 2, cc = lane & 3;
#pragma unroll
    for (int im = 0; im < 4; im++) {
        int row0 = bm + wm + im * 16 + g;
#pragma unroll
        for (int j = 0; j < 4; j++) {
            int col = bn + wn + j * 8 + cc * 2;
            float b0 = bias[col], b1 = bias[col + 1];
            float v0 = acc[im][j][0] + b0, v1 = acc[im][j][1] + b1;
            float v2 = acc[im][j][2] + b0, v3 = acc[im][j][3] + b1;
            if (EPI == 1) {
                v0 = 0.5f * v0 * (1.f + erff(v0 * 0.70710678118654752f));
                v1 = 0.5f * v1 * (1.f + erff(v1 * 0.70710678118654752f));
                v2 = 0.5f * v2 * (1.f + erff(v2 * 0.70710678118654752f));
                v3 = 0.5f * v3 * (1.f + erff(v3 * 0.70710678118654752f));
            }
            if (EPI == 2) {
                float2 r0v = *(const float2*)&res[(size_t)row0 * N + col];
                float2 r1v = *(const float2*)&res[(size_t)(row0 + 8) * N + col];
                v0 += r0v.x; v1 += r0v.y; v2 += r1v.x; v3 += r1v.y;
            }
            if (EPI == 3) {
                v0 = fmaxf(v0, 0.f); v1 = fmaxf(v1, 0.f);
                v2 = fmaxf(v2, 0.f); v3 = fmaxf(v3, 0.f);
            }
            if (OHALF) {
                *(__half2*)&C16[(size_t)row0 * N + col]       = __floats2half2_rn(v0, v1);
                *(__half2*)&C16[(size_t)(row0 + 8) * N + col] = __floats2half2_rn(v2, v3);
            } else {
                float2 o0; o0.x = v0; o0.y = v1;
                float2 o1; o1.x = v2; o1.y = v3;
                *(float2*)&C[(size_t)row0 * N + col] = o0;
                *(float2*)&C[(size_t)(row0 + 8) * N + col] = o1;
            }
        }
    }
}

// ---------------------------------------------------------------------------
// Depthwise 3x3x3 conv, channels-last; fp16 out
// ---------------------------------------------------------------------------
__global__ __launch_bounds__(256)
void dwconv_k(const float* __restrict__ in, const float* __restrict__ w,
              __half* __restrict__ out) {
    __shared__ float ws[256 * 27];
    int tid = threadIdx.x;
    for (int idx = tid; idx < 256 * 27; idx += 256) ws[idx] = w[idx];
    __syncthreads();
    int bx = blockIdx.x;
    int tc = bx & 3;  bx >>= 2;
    int wp = bx & 31; bx >>= 5;
    int hp = bx & 31; bx >>= 5;
    int b  = bx;
    int c  = tid;
    const float* ib = in  + (size_t)b * L * CH;
    __half*      ob = out + (size_t)b * L * CH;
#pragma unroll
    for (int tt = 0; tt < 8; tt++) {
        int t = tc * 8 + tt;
        float acc = 0.f;
#pragma unroll
        for (int dh = -1; dh <= 1; dh++) {
            int h2 = hp + dh; if (h2 < 0 || h2 > 31) continue;
#pragma unroll
            for (int dw = -1; dw <= 1; dw++) {
                int w2 = wp + dw; if (w2 < 0 || w2 > 31) continue;
#pragma unroll
                for (int dt = -1; dt <= 1; dt++) {
                    int t2 = t + dt; if (t2 < 0 || t2 > 31) continue;
                    acc += ws[c * 27 + (dh + 1) * 9 + (dw + 1) * 3 + (dt + 1)] *
                           ib[(size_t)(h2 * 1024 + w2 * 32 + t2) * CH + c];
                }
            }
        }
        ob[(size_t)(hp * 1024 + wp * 32 + t) * CH + c] = __float2half_rn(acc);
    }
}

// ---------------------------------------------------------------------------
// Launch
// ---------------------------------------------------------------------------
extern "C" void kernel_launch(void* const* d_in, const int* in_sizes, int n_in,
                              void* d_out, int out_size) {
    const float* x      = (const float*)d_in[0];
    const float* g1     = (const float*)d_in[1];
    const float* b1     = (const float*)d_in[2];
    const float* qkv_w  = (const float*)d_in[3];
    const float* qkv_b  = (const float*)d_in[4];
    const float* proj_w = (const float*)d_in[5];
    const float* proj_b = (const float*)d_in[6];
    const float* rpb    = (const float*)d_in[7];
    const float* g2     = (const float*)d_in[8];
    const float* b2     = (const float*)d_in[9];
    const float* fc1_w  = (const float*)d_in[10];
    const float* fc1_b  = (const float*)d_in[11];
    const float* fc2_w  = (const float*)d_in[12];
    const float* fc2_b  = (const float*)d_in[13];
    const float* dw_w   = (const float*)d_in[14];
    const float* pw_w   = (const float*)d_in[15];
    const float* pw_b   = (const float*)d_in[16];
    float* out = (float*)d_out;

    float *ph, *ptab;
    __half *hwin, *hqkv, *hmid, *hwts, *hpwT;
    cudaGetSymbolAddress((void**)&ph,   g_h);
    cudaGetSymbolAddress((void**)&hwin, g_win);
    cudaGetSymbolAddress((void**)&hqkv, g_qkv);
    cudaGetSymbolAddress((void**)&hmid, g_mid);
    cudaGetSymbolAddress((void**)&hwts, g_wts);
    cudaGetSymbolAddress((void**)&hpwT, g_pwT);
    cudaGetSymbolAddress((void**)&ptab, g_tab);
    float* fscratch = (float*)hqkv;   // fp32 view for proj/pw outputs

    cudaFuncSetAttribute(hgemm_k<0, 1>, cudaFuncAttributeMaxDynamicSharedMemorySize, HG_SMEM);
    cudaFuncSetAttribute(hgemm_k<0, 0>, cudaFuncAttributeMaxDynamicSharedMemorySize, HG_SMEM);
    cudaFuncSetAttribute(hgemm_k<1, 1>, cudaFuncAttributeMaxDynamicSharedMemorySize, HG_SMEM);
    cudaFuncSetAttribute(hgemm_k<2, 0>, cudaFuncAttributeMaxDynamicSharedMemorySize, HG_SMEM);
    cudaFuncSetAttribute(hgemm_k<3, 0>, cudaFuncAttributeMaxDynamicSharedMemorySize, HG_SMEM);

    // weight prepass: [K][N] -> [N][K] fp16
    wtransH_k<<<dim3(8, 24, 4), dim3(32, 8)>>>(qkv_w,  hwts + W_QKV,  256, 768);
    wtransH_k<<<dim3(8, 8, 4),  dim3(32, 8)>>>(proj_w, hwts + W_PROJ, 256, 256);
    wtransH_k<<<dim3(8, 32, 4), dim3(32, 8)>>>(fc1_w,  hwts + W_FC1,  256, 1024);
    wtransH_k<<<dim3(32, 8, 4), dim3(32, 8)>>>(fc2_w,  hwts + W_FC2,  1024, 256);
    cvt_k<<<256, 256>>>(pw_w, hpwT, 65536);       // [co][ci] already [N][K]

    // x [b][c][p] -> h [b][p][c]
    transpose_k<<<dim3(8, 1024, 2), dim3(32, 8)>>>(x, ph, 256, 32768);

    for (int blk = 0; blk < 4; blk++) {
        int shift = (blk & 1) ? 2 : 0;
        ln_winpart_k<<<MROWS, 256>>>(ph, g1 + blk * 256, b1 + blk * 256, hwin, shift);
        hgemm_k<0, 1><<<dim3(6, 512), 256, HG_SMEM>>>(
            hwin, hwts + W_QKV + (size_t)blk * 256 * 768, qkv_b + blk * 768, nullptr,
            nullptr, hqkv, MROWS, 768, 256);
        attn_tab_k<<<64, 64>>>(rpb + blk * 343 * 8, ptab, shift);
        attn_k<<<TOTW * 2, 128>>>(hqkv, ptab, hwin, shift);
        hgemm_k<0, 0><<<dim3(2, 512), 256, HG_SMEM>>>(
            hwin, hwts + W_PROJ + (size_t)blk * 256 * 256, proj_b + blk * 256, nullptr,
            fscratch, nullptr, MROWS, 256, 256);
        winrev_ln_k<<<MROWS, 256>>>(fscratch, ph, g2 + blk * 256, b2 + blk * 256, hwin, shift);
        hgemm_k<1, 1><<<dim3(8, 512), 256, HG_SMEM>>>(
            hwin, hwts + W_FC1 + (size_t)blk * 256 * 1024, fc1_b + blk * 1024, nullptr,
            nullptr, hmid, MROWS, 1024, 256);
        hgemm_k<2, 0><<<dim3(2, 512), 256, HG_SMEM>>>(
            hmid, hwts + W_FC2 + (size_t)blk * 1024 * 256, fc2_b + blk * 256, ph,
            ph, nullptr, MROWS, 256, 1024);
    }

    dwconv_k<<<BATCH * 32 * 32 * 4, 256>>>(ph, dw_w, hwin);
    hgemm_k<3, 0><<<dim3(2, 512), 256, HG_SMEM>>>(
        hwin, hpwT, pw_b, nullptr, fscratch, nullptr, MROWS, 256, 256);
    transpose_k<<<dim3(1024, 8, 2), dim3(32, 8)>>>(fscratch, out, 32768, 256);
}

// round 15
// speedup vs baseline: 1.1462x; 1.0868x over previous
#include <cuda_runtime.h>
#include <cuda_fp16.h>
#include <math.h>
#include <stdint.h>

// ---------------------------------------------------------------------------
// Problem constants
// ---------------------------------------------------------------------------
#define BATCH 2
#define CH    256
#define L     32768
#define NH    8
#define TOTW  1024
#define MROWS 65536

// ---------------------------------------------------------------------------
// Scratch (device globals; allocation-free)
// ---------------------------------------------------------------------------
__device__ float  g_h[(size_t)BATCH * L * CH];      // residual stream fp32 [b][p][c]
__device__ __half g_win[(size_t)MROWS * CH];        // fp16 activations (GEMM A)
__device__ __half g_qkv[(size_t)MROWS * 768];       // fp16 qkv; also fp32-view scratch
__device__ __half g_mid[(size_t)MROWS * 1024];      // fp16 MLP hidden
__device__ __half g_wts[3145728];                   // fp16 weights, [N][K]
__device__ __half g_pwT[CH * CH];                   // fp16 pointwise W [co][ci]=[N][K]
__device__ float  g_tab[8 * 8 * 64 * 64];           // attn bias+mask table

#define W_QKV 0
#define W_PROJ 786432
#define W_FC1 1048576
#define W_FC2 2097152

// ---------------------------------------------------------------------------
// Batched 2D transpose (fp32, for harness I/O layout)
// ---------------------------------------------------------------------------
__global__ void transpose_k(const float* __restrict__ in, float* __restrict__ out,
                            int R, int Cc) {
    __shared__ float tile[32][33];
    int b  = blockIdx.z;
    int r0 = blockIdx.x * 32, c0 = blockIdx.y * 32;
    const float* ib = in  + (size_t)b * R * Cc;
    float*       ob = out + (size_t)b * R * Cc;
    int tx = threadIdx.x, ty = threadIdx.y;
#pragma unroll
    for (int i = 0; i < 4; i++)
        tile[ty + i * 8][tx] = ib[(size_t)(r0 + ty + i * 8) * Cc + c0 + tx];
    __syncthreads();
#pragma unroll
    for (int i = 0; i < 4; i++)
        ob[(size_t)(c0 + ty + i * 8) * R + r0 + tx] = tile[tx][ty + i * 8];
}

// Transpose + fp16-convert weights: [R][C] -> [C][R], batched over z
__global__ void wtransH_k(const float* __restrict__ in, __half* __restrict__ out,
                          int R, int Cc) {
    __shared__ float tile[32][33];
    int b  = blockIdx.z;
    int r0 = blockIdx.x * 32, c0 = blockIdx.y * 32;
    const float* ib = in  + (size_t)b * R * Cc;
    __half*      ob = out + (size_t)b * R * Cc;
    int tx = threadIdx.x, ty = threadIdx.y;
#pragma unroll
    for (int i = 0; i < 4; i++)
        tile[ty + i * 8][tx] = ib[(size_t)(r0 + ty + i * 8) * Cc + c0 + tx];
    __syncthreads();
#pragma unroll
    for (int i = 0; i < 4; i++)
        ob[(size_t)(c0 + ty + i * 8) * R + r0 + tx] = __float2half_rn(tile[tx][ty + i * 8]);
}

// Convert only (fp32 -> fp16)
__global__ void cvt_k(const float* __restrict__ src, __half* __restrict__ dst, int n) {
    int i = blockIdx.x * 256 + threadIdx.x;
    if (i < n) dst[i] = __float2half_rn(src[i]);
}

// ---------------------------------------------------------------------------
// Window-token index -> source row (fused roll)
// ---------------------------------------------------------------------------
__device__ __forceinline__ int decomp_win(int wt_idx, int shift) {
    int widx = wt_idx >> 6, n = wt_idx & 63;
    int b = widx >> 9;  int wr = widx & 511;
    int wh = wr >> 6, ww = (wr >> 3) & 7, wt = wr & 7;
    int i = n >> 4, j = (n >> 2) & 3, k = n & 3;
    int gh = (wh * 4 + i + shift) & 31;
    int gw = (ww * 4 + j + shift) & 31;
    int gt = (wt * 4 + k + shift) & 31;
    return b * L + gh * 1024 + gw * 32 + gt;
}

// Warp-level mean/var of 8 values per lane (256 channels per warp).
__device__ __forceinline__ void warp_stats(const float* v, float& mean, float& var) {
    float s1 = 0.f, s2 = 0.f;
#pragma unroll
    for (int i = 0; i < 8; i++) { s1 += v[i]; s2 += v[i] * v[i]; }
#pragma unroll
    for (int o = 16; o > 0; o >>= 1) {
        s1 += __shfl_xor_sync(0xFFFFFFFFu, s1, o);
        s2 += __shfl_xor_sync(0xFFFFFFFFu, s2, o);
    }
    mean = s1 * (1.f / 256.f);
    var  = s2 * (1.f / 256.f) - mean * mean;
}

// LN + roll + window-partition; warp-per-token (8 tokens/block), fp16 out
__global__ __launch_bounds__(256)
void ln_winpart_k(const float* __restrict__ h, const float* __restrict__ g,
                  const float* __restrict__ be, __half* __restrict__ out,
                  int shift) {
    int warp = threadIdx.x >> 5, lane = threadIdx.x & 31;
    int wt = blockIdx.x * 8 + warp;          // window-token index
    int srow = decomp_win(wt, shift);
    int c0 = lane * 8;
    float v[8];
    *(float4*)(v)     = *(const float4*)&h[(size_t)srow * CH + c0];
    *(float4*)(v + 4) = *(const float4*)&h[(size_t)srow * CH + c0 + 4];
    float mean, var;
    warp_stats(v, mean, var);
    float rstd = rsqrtf(var + 1e-5f);
    __half hv[8];
#pragma unroll
    for (int i = 0; i < 8; i++)
        hv[i] = __float2half_rn((v[i] - mean) * rstd * g[c0 + i] + be[c0 + i]);
    *(float4*)&out[(size_t)wt * CH + c0] = *(float4*)hv;
}

// Window reverse + residual add + LN2 fused; warp-per-token; fp16 out
__global__ __launch_bounds__(256)
void winrev_ln_k(const float* __restrict__ p, float* __restrict__ h,
                 const float* __restrict__ g, const float* __restrict__ be,
                 __half* __restrict__ out, int shift) {
    int warp = threadIdx.x >> 5, lane = threadIdx.x & 31;
    int wt = blockIdx.x * 8 + warp;
    int srow = decomp_win(wt, shift);
    int c0 = lane * 8;
    float v[8], pv[8];
    *(float4*)(v)      = *(const float4*)&h[(size_t)srow * CH + c0];
    *(float4*)(v + 4)  = *(const float4*)&h[(size_t)srow * CH + c0 + 4];
    *(float4*)(pv)     = *(const float4*)&p[(size_t)wt * CH + c0];
    *(float4*)(pv + 4) = *(const float4*)&p[(size_t)wt * CH + c0 + 4];
#pragma unroll
    for (int i = 0; i < 8; i++) v[i] += pv[i];
    *(float4*)&h[(size_t)srow * CH + c0]     = *(float4*)(v);
    *(float4*)&h[(size_t)srow * CH + c0 + 4] = *(float4*)(v + 4);
    float mean, var;
    warp_stats(v, mean, var);
    float rstd = rsqrtf(var + 1e-5f);
    __half hv[8];
#pragma unroll
    for (int i = 0; i < 8; i++)
        hv[i] = __float2half_rn((v[i] - mean) * rstd * g[c0 + i] + be[c0 + i]);
    *(float4*)&out[(size_t)srow * CH + c0] = *(float4*)hv;
}

// ---------------------------------------------------------------------------
// Attention bias+mask table
// ---------------------------------------------------------------------------
__device__ __forceinline__ int axlab(int border, int i) {
    return border ? (i >= 2 ? 2 : 1) : 0;
}

__global__ void attn_tab_k(const float* __restrict__ rpb, float* __restrict__ tab,
                           int shift) {
    int cls = blockIdx.x >> 3, head = blockIdx.x & 7;
    int r = threadIdx.x;
    int bh = (cls >> 2) & 1, bw = (cls >> 1) & 1, bt = cls & 1;
    int ri = r >> 4, rj = (r >> 2) & 3, rk = r & 3;
    int labr = axlab(bh, ri) * 9 + axlab(bw, rj) * 3 + axlab(bt, rk);
    float* dst = tab + ((size_t)(cls * 8 + head) * 64 + r) * 64;
    for (int m = 0; m < 64; m++) {
        int mi = m >> 4, mj = (m >> 2) & 3, mk = m & 3;
        float v = rpb[((ri - mi + 3) * 49 + (rj - mj + 3) * 7 + (rk - mk + 3)) * 8 + head];
        if (shift) {
            int labm = axlab(bh, mi) * 9 + axlab(bw, mj) * 3 + axlab(bt, mk);
            if (labm != labr) v -= 100.f;
        }
        dst[m] = v;
    }
}

// ---------------------------------------------------------------------------
// Tensor-core windowed attention: one WARP per (window, head).
// ---------------------------------------------------------------------------
__device__ __forceinline__ void mma16816a(float* d, uint32_t a0, uint32_t a1,
                                          uint32_t a2, uint32_t a3,
                                          uint32_t b0, uint32_t b1) {
    asm volatile(
        "mma.sync.aligned.m16n8k16.row.col.f32.f16.f16.f32 "
        "{%0,%1,%2,%3},{%4,%5,%6,%7},{%8,%9},{%0,%1,%2,%3};"
        : "+f"(d[0]), "+f"(d[1]), "+f"(d[2]), "+f"(d[3])
        : "r"(a0), "r"(a1), "r"(a2), "r"(a3), "r"(b0), "r"(b1));
}
__device__ __forceinline__ uint32_t h2u(__half2 h) { return *(uint32_t*)&h; }

__global__ __launch_bounds__(128)
void attn_k(const __half* __restrict__ qkv, const float* __restrict__ tab,
            __half* __restrict__ o, int shift) {
    int widx = blockIdx.x >> 1;
    int head = (blockIdx.x & 1) * 4 + (threadIdx.x >> 5);
    int lane = threadIdx.x & 31;
    int g = lane >> 2, cc = lane & 3;

    const __half* base = qkv + (size_t)widx * 64 * 768;
    const __half* Q = base + head * 32;
    const __half* K = base + 256 + head * 32;
    const __half* V = base + 512 + head * 32;

    int cls = 0;
    if (shift) {
        int wr = widx & 511;
        cls = (((wr >> 6) == 7) << 2) | ((((wr >> 3) & 7) == 7) << 1) | ((wr & 7) == 7);
    }
    const float* T = tab + (size_t)(cls * 8 + head) * 4096;

    // ---- S = Q K^T  (64x64x32) ----
    float S[4][8][4];
#pragma unroll
    for (int i = 0; i < 4; i++)
#pragma unroll
        for (int j = 0; j < 8; j++)
#pragma unroll
            for (int c = 0; c < 4; c++) S[i][j][c] = 0.f;

#pragma unroll
    for (int t = 0; t < 2; t++) {
        uint32_t a[4][4];
#pragma unroll
        for (int i = 0; i < 4; i++) {
            const __half* q0 = Q + (size_t)(16 * i + g) * 768 + t * 16 + 2 * cc;
            a[i][0] = *(const uint32_t*)(q0);
            a[i][1] = *(const uint32_t*)(q0 + 8 * 768);
            a[i][2] = *(const uint32_t*)(q0 + 8);
            a[i][3] = *(const uint32_t*)(q0 + 8 * 768 + 8);
        }
        uint32_t bq[8][2];
#pragma unroll
        for (int j = 0; j < 8; j++) {
            const __half* k0 = K + (size_t)(8 * j + g) * 768 + t * 16 + 2 * cc;
            bq[j][0] = *(const uint32_t*)(k0);
            bq[j][1] = *(const uint32_t*)(k0 + 8);
        }
#pragma unroll
        for (int i = 0; i < 4; i++)
#pragma unroll
            for (int j = 0; j < 8; j++)
                mma16816a(S[i][j], a[i][0], a[i][1], a[i][2], a[i][3],
                          bq[j][0], bq[j][1]);
    }

    // ---- scale + bias ----
    const float sc = 0.17677669529663687f;
#pragma unroll
    for (int i = 0; i < 4; i++)
#pragma unroll
        for (int j = 0; j < 8; j++) {
            float2 t0 = *(const float2*)&T[(16 * i + g) * 64 + 8 * j + 2 * cc];
            float2 t1 = *(const float2*)&T[(16 * i + g + 8) * 64 + 8 * j + 2 * cc];
            S[i][j][0] = S[i][j][0] * sc + t0.x;
            S[i][j][1] = S[i][j][1] * sc + t0.y;
            S[i][j][2] = S[i][j][2] * sc + t1.x;
            S[i][j][3] = S[i][j][3] * sc + t1.y;
        }

    // ---- softmax ----
    float inv0[4], inv1[4];
#pragma unroll
    for (int i = 0; i < 4; i++) {
        float m0 = -1e30f, m1 = -1e30f;
#pragma unroll
        for (int j = 0; j < 8; j++) {
            m0 = fmaxf(m0, fmaxf(S[i][j][0], S[i][j][1]));
            m1 = fmaxf(m1, fmaxf(S[i][j][2], S[i][j][3]));
        }
        m0 = fmaxf(m0, __shfl_xor_sync(0xFFFFFFFFu, m0, 1));
        m0 = fmaxf(m0, __shfl_xor_sync(0xFFFFFFFFu, m0, 2));
        m1 = fmaxf(m1, __shfl_xor_sync(0xFFFFFFFFu, m1, 1));
        m1 = fmaxf(m1, __shfl_xor_sync(0xFFFFFFFFu, m1, 2));
        float s0 = 0.f, s1 = 0.f;
#pragma unroll
        for (int j = 0; j < 8; j++) {
            float e0 = __expf(S[i][j][0] - m0);
            float e1 = __expf(S[i][j][1] - m0);
            float e2 = __expf(S[i][j][2] - m1);
            float e3 = __expf(S[i][j][3] - m1);
            S[i][j][0] = e0; S[i][j][1] = e1; S[i][j][2] = e2; S[i][j][3] = e3;
            s0 += e0 + e1; s1 += e2 + e3;
        }
        s0 += __shfl_xor_sync(0xFFFFFFFFu, s0, 1);
        s0 += __shfl_xor_sync(0xFFFFFFFFu, s0, 2);
        s1 += __shfl_xor_sync(0xFFFFFFFFu, s1, 1);
        s1 += __shfl_xor_sync(0xFFFFFFFFu, s1, 2);
        inv0[i] = 1.f / s0;
        inv1[i] = 1.f / s1;
    }

    // ---- scores -> fp16 A fragments ----
    uint32_t Sh[4][8][2];
#pragma unroll
    for (int i = 0; i < 4; i++)
#pragma unroll
        for (int j = 0; j < 8; j++) {
            Sh[i][j][0] = h2u(__floats2half2_rn(S[i][j][0], S[i][j][1]));
            Sh[i][j][1] = h2u(__floats2half2_rn(S[i][j][2], S[i][j][3]));
        }

    // ---- O = S V  (64x32x64) ----
    float O[4][4][4];
#pragma unroll
    for (int i = 0; i < 4; i++)
#pragma unroll
        for (int j = 0; j < 4; j++)
#pragma unroll
            for (int c = 0; c < 4; c++) O[i][j][c] = 0.f;

#pragma unroll
    for (int t = 0; t < 4; t++) {
        uint32_t bv[4][2];
#pragma unroll
        for (int j = 0; j < 4; j++) {
            const __half* v0 = V + (size_t)(16 * t + 2 * cc) * 768 + 8 * j + g;
            bv[j][0] = h2u(__halves2half2(v0[0], v0[768]));
            bv[j][1] = h2u(__halves2half2(v0[8 * 768], v0[9 * 768]));
        }
#pragma unroll
        for (int i = 0; i < 4; i++)
#pragma unroll
            for (int j = 0; j < 4; j++)
                mma16816a(O[i][j], Sh[i][2 * t][0], Sh[i][2 * t][1],
                          Sh[i][2 * t + 1][0], Sh[i][2 * t + 1][1],
                          bv[j][0], bv[j][1]);
    }

    // ---- write out ----
    __half* ob = o + (size_t)widx * 64 * CH + head * 32;
#pragma unroll
    for (int i = 0; i < 4; i++) {
        int r0 = 16 * i + g;
#pragma unroll
        for (int j = 0; j < 4; j++) {
            int col = 8 * j + 2 * cc;
            *(__half2*)(ob + (size_t)r0 * CH + col) =
                __floats2half2_rn(O[i][j][0] * inv0[i], O[i][j][1] * inv0[i]);
            *(__half2*)(ob + (size_t)(r0 + 8) * CH + col) =
                __floats2half2_rn(O[i][j][2] * inv1[i], O[i][j][3] * inv1[i]);
        }
    }
}

// ---------------------------------------------------------------------------
// FP16 tensor-core GEMM: mma.sync.m16n8k16, ldmatrix fragments.
// R12 config (best measured): block tile 128x128, 8 warps (2x4), warp tile
// 64x32, K-tile 32 halves, TWO-stage cp.async issue-before-wait, 2 CTAs/SM.
// B=W^T [N][K]; non-trans ldmatrix for B. RSTR=40 pad.
// EPI: 0 bias, 1 bias+GELU, 2 bias+residual, 3 bias+ReLU. OHALF: fp16 out.
// ---------------------------------------------------------------------------
#define RSTR 40                           // halves per smem row
#define ASTAGE (128 * RSTR)               // halves
#define BSTAGE (128 * RSTR)
#define HG_SMEM ((2 * ASTAGE + 2 * BSTAGE) * 2)   // 40960 bytes

__device__ __forceinline__ uint32_t smem_u32(const void* p) {
    uint32_t a;
    asm("{ .reg .u64 t; cvta.to.shared.u64 t, %1; cvt.u32.u64 %0, t; }" : "=r"(a) : "l"(p));
    return a;
}
__device__ __forceinline__ void cp16(uint32_t dst, const void* src) {
    asm volatile("cp.async.cg.shared.global [%0], [%1], 16;\n" :: "r"(dst), "l"(src));
}
__device__ __forceinline__ void ldm4(uint32_t* f, uint32_t a) {
    asm volatile("ldmatrix.sync.aligned.m8n8.x4.shared.b16 {%0,%1,%2,%3}, [%4];"
                 : "=r"(f[0]), "=r"(f[1]), "=r"(f[2]), "=r"(f[3]) : "r"(a));
}
__device__ __forceinline__ void mma16816(float* d, const uint32_t* a, uint32_t b0, uint32_t b1) {
    asm volatile(
        "mma.sync.aligned.m16n8k16.row.col.f32.f16.f16.f32 "
        "{%0,%1,%2,%3},{%4,%5,%6,%7},{%8,%9},{%0,%1,%2,%3};"
        : "+f"(d[0]), "+f"(d[1]), "+f"(d[2]), "+f"(d[3])
        : "r"(a[0]), "r"(a[1]), "r"(a[2]), "r"(a[3]), "r"(b0), "r"(b1));
}

template <int EPI, int OHALF>
__global__ __launch_bounds__(256, 2)
void hgemm_k(const __half* __restrict__ A, const __half* __restrict__ Bw,
             const float* __restrict__ bias, const float* __restrict__ res,
             float* __restrict__ C, __half* __restrict__ C16, int M, int N, int K) {
    extern __shared__ __half sh[];
    uint32_t sA[2], sB[2];
    sA[0] = smem_u32(sh);
    sA[1] = sA[0] + ASTAGE * 2;
    sB[0] = sA[1] + ASTAGE * 2;
    sB[1] = sB[0] + BSTAGE * 2;

    int tid = threadIdx.x, lane = tid & 31, warp = tid >> 5;
    int wm = (warp & 1) * 64, wn = (warp >> 1) * 32;
    int bm = blockIdx.y * 128, bn = blockIdx.x * 128;

    uint32_t aoff = (uint32_t)(lane & 15) * (RSTR * 2) + ((lane >> 4) & 1) * 16;
    uint32_t boff = (uint32_t)((lane & 7) + ((lane >> 4) & 1) * 8) * (RSTR * 2)
                  + ((lane >> 3) & 1) * 16;

    int arow = tid >> 1, ach = (tid & 1) * 2;
    const __half* Ag = A + (size_t)(bm + arow) * K + ach * 8;
    const __half* Bg = Bw + (size_t)(bn + arow) * K + ach * 8;
    uint32_t adst = (uint32_t)arow * (RSTR * 2) + ach * 16;

    float acc[4][4][4];
#pragma unroll
    for (int i = 0; i < 4; i++)
#pragma unroll
        for (int j = 0; j < 4; j++)
#pragma unroll
            for (int c2 = 0; c2 < 4; c2++) acc[i][j][c2] = 0.f;

    int nkt = K >> 5;

    cp16(sA[0] + adst,      Ag);
    cp16(sA[0] + adst + 16, Ag + 8);
    cp16(sB[0] + adst,      Bg);
    cp16(sB[0] + adst + 16, Bg + 8);
    asm volatile("cp.async.commit_group;\n");

    int buf = 0;
    for (int kt = 0; kt < nkt; kt++) {
        if (kt + 1 < nkt) {
            int ko = (kt + 1) * 32;
            uint32_t da = sA[buf ^ 1], db = sB[buf ^ 1];
            cp16(da + adst,      Ag + ko);
            cp16(da + adst + 16, Ag + ko + 8);
            cp16(db + adst,      Bg + ko);
            cp16(db + adst + 16, Bg + ko + 8);
            asm volatile("cp.async.commit_group;\n");
            asm volatile("cp.async.wait_group 1;\n");
        } else {
            asm volatile("cp.async.wait_group 0;\n");
        }
        __syncthreads();

        uint32_t sa = sA[buf], sbb = sB[buf];
#pragma unroll
        for (int kk = 0; kk < 2; kk++) {
            uint32_t af[4][4], bf[2][4];
#pragma unroll
            for (int im = 0; im < 4; im++)
                ldm4(af[im], sa + (uint32_t)(wm + im * 16) * (RSTR * 2) + kk * 32 + aoff);
#pragma unroll
            for (int jn = 0; jn < 2; jn++)
                ldm4(bf[jn], sbb + (uint32_t)(wn + jn * 16) * (RSTR * 2) + kk * 32 + boff);
#pragma unroll
            for (int im = 0; im < 4; im++)
#pragma unroll
                for (int jn = 0; jn < 2; jn++) {
                    mma16816(acc[im][jn * 2],     af[im], bf[jn][0], bf[jn][1]);
                    mma16816(acc[im][jn * 2 + 1], af[im], bf[jn][2], bf[jn][3]);
                }
        }
        __syncthreads();
        buf ^= 1;
    }

    int g = lane >> 2, cc = lane & 3;
#pragma unroll
    for (int im = 0; im < 4; im++) {
        int row0 = bm + wm + im * 16 + g;
#pragma unroll
        for (int j = 0; j < 4; j++) {
            int col = bn + wn + j * 8 + cc * 2;
            float b0 = bias[col], b1 = bias[col + 1];
            float v0 = acc[im][j][0] + b0, v1 = acc[im][j][1] + b1;
            float v2 = acc[im][j][2] + b0, v3 = acc[im][j][3] + b1;
            if (EPI == 1) {
                v0 = 0.5f * v0 * (1.f + erff(v0 * 0.70710678118654752f));
                v1 = 0.5f * v1 * (1.f + erff(v1 * 0.70710678118654752f));
                v2 = 0.5f * v2 * (1.f + erff(v2 * 0.70710678118654752f));
                v3 = 0.5f * v3 * (1.f + erff(v3 * 0.70710678118654752f));
            }
            if (EPI == 2) {
                float2 r0v = *(const float2*)&res[(size_t)row0 * N + col];
                float2 r1v = *(const float2*)&res[(size_t)(row0 + 8) * N + col];
                v0 += r0v.x; v1 += r0v.y; v2 += r1v.x; v3 += r1v.y;
            }
            if (EPI == 3) {
                v0 = fmaxf(v0, 0.f); v1 = fmaxf(v1, 0.f);
                v2 = fmaxf(v2, 0.f); v3 = fmaxf(v3, 0.f);
            }
            if (OHALF) {
                *(__half2*)&C16[(size_t)row0 * N + col]       = __floats2half2_rn(v0, v1);
                *(__half2*)&C16[(size_t)(row0 + 8) * N + col] = __floats2half2_rn(v2, v3);
            } else {
                float2 o0; o0.x = v0; o0.y = v1;
                float2 o1; o1.x = v2; o1.y = v3;
                *(float2*)&C[(size_t)row0 * N + col] = o0;
                *(float2*)&C[(size_t)(row0 + 8) * N + col] = o1;
            }
        }
    }
}

// ---------------------------------------------------------------------------
// Depthwise 3x3x3 conv, channels-last; fp16 out
// ---------------------------------------------------------------------------
__global__ __launch_bounds__(256)
void dwconv_k(const float* __restrict__ in, const float* __restrict__ w,
              __half* __restrict__ out) {
    __shared__ float ws[256 * 27];
    int tid = threadIdx.x;
    for (int idx = tid; idx < 256 * 27; idx += 256) ws[idx] = w[idx];
    __syncthreads();
    int bx = blockIdx.x;
    int tc = bx & 3;  bx >>= 2;
    int wp = bx & 31; bx >>= 5;
    int hp = bx & 31; bx >>= 5;
    int b  = bx;
    int c  = tid;
    const float* ib = in  + (size_t)b * L * CH;
    __half*      ob = out + (size_t)b * L * CH;
#pragma unroll
    for (int tt = 0; tt < 8; tt++) {
        int t = tc * 8 + tt;
        float acc = 0.f;
#pragma unroll
        for (int dh = -1; dh <= 1; dh++) {
            int h2 = hp + dh; if (h2 < 0 || h2 > 31) continue;
#pragma unroll
            for (int dw = -1; dw <= 1; dw++) {
                int w2 = wp + dw; if (w2 < 0 || w2 > 31) continue;
#pragma unroll
                for (int dt = -1; dt <= 1; dt++) {
                    int t2 = t + dt; if (t2 < 0 || t2 > 31) continue;
                    acc += ws[c * 27 + (dh + 1) * 9 + (dw + 1) * 3 + (dt + 1)] *
                           ib[(size_t)(h2 * 1024 + w2 * 32 + t2) * CH + c];
                }
            }
        }
        ob[(size_t)(hp * 1024 + wp * 32 + t) * CH + c] = __float2half_rn(acc);
    }
}

// ---------------------------------------------------------------------------
// Launch
// ---------------------------------------------------------------------------
extern "C" void kernel_launch(void* const* d_in, const int* in_sizes, int n_in,
                              void* d_out, int out_size) {
    const float* x      = (const float*)d_in[0];
    const float* g1     = (const float*)d_in[1];
    const float* b1     = (const float*)d_in[2];
    const float* qkv_w  = (const float*)d_in[3];
    const float* qkv_b  = (const float*)d_in[4];
    const float* proj_w = (const float*)d_in[5];
    const float* proj_b = (const float*)d_in[6];
    const float* rpb    = (const float*)d_in[7];
    const float* g2     = (const float*)d_in[8];
    const float* b2     = (const float*)d_in[9];
    const float* fc1_w  = (const float*)d_in[10];
    const float* fc1_b  = (const float*)d_in[11];
    const float* fc2_w  = (const float*)d_in[12];
    const float* fc2_b  = (const float*)d_in[13];
    const float* dw_w   = (const float*)d_in[14];
    const float* pw_w   = (const float*)d_in[15];
    const float* pw_b   = (const float*)d_in[16];
    float* out = (float*)d_out;

    float *ph, *ptab;
    __half *hwin, *hqkv, *hmid, *hwts, *hpwT;
    cudaGetSymbolAddress((void**)&ph,   g_h);
    cudaGetSymbolAddress((void**)&hwin, g_win);
    cudaGetSymbolAddress((void**)&hqkv, g_qkv);
    cudaGetSymbolAddress((void**)&hmid, g_mid);
    cudaGetSymbolAddress((void**)&hwts, g_wts);
    cudaGetSymbolAddress((void**)&hpwT, g_pwT);
    cudaGetSymbolAddress((void**)&ptab, g_tab);
    float* fscratch = (float*)hqkv;   // fp32 view for proj/pw outputs

    // weight prepass: [K][N] -> [N][K] fp16
    wtransH_k<<<dim3(8, 24, 4), dim3(32, 8)>>>(qkv_w,  hwts + W_QKV,  256, 768);
    wtransH_k<<<dim3(8, 8, 4),  dim3(32, 8)>>>(proj_w, hwts + W_PROJ, 256, 256);
    wtransH_k<<<dim3(8, 32, 4), dim3(32, 8)>>>(fc1_w,  hwts + W_FC1,  256, 1024);
    wtransH_k<<<dim3(32, 8, 4), dim3(32, 8)>>>(fc2_w,  hwts + W_FC2,  1024, 256);
    cvt_k<<<256, 256>>>(pw_w, hpwT, 65536);       // [co][ci] already [N][K]

    // x [b][c][p] -> h [b][p][c]
    transpose_k<<<dim3(8, 1024, 2), dim3(32, 8)>>>(x, ph, 256, 32768);

    for (int blk = 0; blk < 4; blk++) {
        int shift = (blk & 1) ? 2 : 0;
        ln_winpart_k<<<MROWS / 8, 256>>>(ph, g1 + blk * 256, b1 + blk * 256, hwin, shift);
        hgemm_k<0, 1><<<dim3(6, 512), 256, HG_SMEM>>>(
            hwin, hwts + W_QKV + (size_t)blk * 256 * 768, qkv_b + blk * 768, nullptr,
            nullptr, hqkv, MROWS, 768, 256);
        attn_tab_k<<<64, 64>>>(rpb + blk * 343 * 8, ptab, shift);
        attn_k<<<TOTW * 2, 128>>>(hqkv, ptab, hwin, shift);
        hgemm_k<0, 0><<<dim3(2, 512), 256, HG_SMEM>>>(
            hwin, hwts + W_PROJ + (size_t)blk * 256 * 256, proj_b + blk * 256, nullptr,
            fscratch, nullptr, MROWS, 256, 256);
        winrev_ln_k<<<MROWS / 8, 256>>>(fscratch, ph, g2 + blk * 256, b2 + blk * 256, hwin, shift);
        hgemm_k<1, 1><<<dim3(8, 512), 256, HG_SMEM>>>(
            hwin, hwts + W_FC1 + (size_t)blk * 256 * 1024, fc1_b + blk * 1024, nullptr,
            nullptr, hmid, MROWS, 1024, 256);
        hgemm_k<2, 0><<<dim3(2, 512), 256, HG_SMEM>>>(
            hmid, hwts + W_FC2 + (size_t)blk * 1024 * 256, fc2_b + blk * 256, ph,
            ph, nullptr, MROWS, 256, 1024);
    }

    dwconv_k<<<BATCH * 32 * 32 * 4, 256>>>(ph, dw_w, hwin);
    hgemm_k<3, 0><<<dim3(2, 512), 256, HG_SMEM>>>(
        hwin, hpwT, pw_b, nullptr, fscratch, nullptr, MROWS, 256, 256);
    transpose_k<<<dim3(1024, 8, 2), dim3(32, 8)>>>(fscratch, out, 32768, 256);
}

// round 16
// speedup vs baseline: 1.1474x; 1.0011x over previous
#include <cuda_runtime.h>
#include <cuda_fp16.h>
#include <math.h>
#include <stdint.h>

// ---------------------------------------------------------------------------
// Problem constants
// ---------------------------------------------------------------------------
#define BATCH 2
#define CH    256
#define L     32768
#define NH    8
#define TOTW  1024
#define MROWS 65536

// ---------------------------------------------------------------------------
// Scratch (device globals; allocation-free)
// ---------------------------------------------------------------------------
__device__ float  g_h[(size_t)BATCH * L * CH];      // residual stream fp32 [b][p][c]
__device__ __half g_win[(size_t)MROWS * CH];        // fp16 activations (GEMM A)
__device__ __half g_qkv[(size_t)MROWS * 768];       // fp16 qkv; also fp32-view scratch
__device__ __half g_mid[(size_t)MROWS * 1024];      // fp16 MLP hidden
__device__ __half g_wts[3145728];                   // fp16 weights, [N][K]
__device__ __half g_pwT[CH * CH];                   // fp16 pointwise W [co][ci]=[N][K]
__device__ float  g_tab[8 * 8 * 64 * 64];           // attn bias+mask table

#define W_QKV 0
#define W_PROJ 786432
#define W_FC1 1048576
#define W_FC2 2097152

// ---------------------------------------------------------------------------
// Batched 2D transpose (fp32, for harness I/O layout)
// ---------------------------------------------------------------------------
__global__ void transpose_k(const float* __restrict__ in, float* __restrict__ out,
                            int R, int Cc) {
    __shared__ float tile[32][33];
    int b  = blockIdx.z;
    int r0 = blockIdx.x * 32, c0 = blockIdx.y * 32;
    const float* ib = in  + (size_t)b * R * Cc;
    float*       ob = out + (size_t)b * R * Cc;
    int tx = threadIdx.x, ty = threadIdx.y;
#pragma unroll
    for (int i = 0; i < 4; i++)
        tile[ty + i * 8][tx] = ib[(size_t)(r0 + ty + i * 8) * Cc + c0 + tx];
    __syncthreads();
#pragma unroll
    for (int i = 0; i < 4; i++)
        ob[(size_t)(c0 + ty + i * 8) * R + r0 + tx] = tile[tx][ty + i * 8];
}

// Transpose + fp16-convert weights: [R][C] -> [C][R], batched over z
__global__ void wtransH_k(const float* __restrict__ in, __half* __restrict__ out,
                          int R, int Cc) {
    __shared__ float tile[32][33];
    int b  = blockIdx.z;
    int r0 = blockIdx.x * 32, c0 = blockIdx.y * 32;
    const float* ib = in  + (size_t)b * R * Cc;
    __half*      ob = out + (size_t)b * R * Cc;
    int tx = threadIdx.x, ty = threadIdx.y;
#pragma unroll
    for (int i = 0; i < 4; i++)
        tile[ty + i * 8][tx] = ib[(size_t)(r0 + ty + i * 8) * Cc + c0 + tx];
    __syncthreads();
#pragma unroll
    for (int i = 0; i < 4; i++)
        ob[(size_t)(c0 + ty + i * 8) * R + r0 + tx] = __float2half_rn(tile[tx][ty + i * 8]);
}

// Convert only (fp32 -> fp16)
__global__ void cvt_k(const float* __restrict__ src, __half* __restrict__ dst, int n) {
    int i = blockIdx.x * 256 + threadIdx.x;
    if (i < n) dst[i] = __float2half_rn(src[i]);
}

// ---------------------------------------------------------------------------
// Window-token index -> source row (fused roll)
// ---------------------------------------------------------------------------
__device__ __forceinline__ int decomp_win(int wt_idx, int shift) {
    int widx = wt_idx >> 6, n = wt_idx & 63;
    int b = widx >> 9;  int wr = widx & 511;
    int wh = wr >> 6, ww = (wr >> 3) & 7, wt = wr & 7;
    int i = n >> 4, j = (n >> 2) & 3, k = n & 3;
    int gh = (wh * 4 + i + shift) & 31;
    int gw = (ww * 4 + j + shift) & 31;
    int gt = (wt * 4 + k + shift) & 31;
    return b * L + gh * 1024 + gw * 32 + gt;
}

// Warp-level mean/var of 8 values per lane (256 channels per warp).
__device__ __forceinline__ void warp_stats(const float* v, float& mean, float& var) {
    float s1 = 0.f, s2 = 0.f;
#pragma unroll
    for (int i = 0; i < 8; i++) { s1 += v[i]; s2 += v[i] * v[i]; }
#pragma unroll
    for (int o = 16; o > 0; o >>= 1) {
        s1 += __shfl_xor_sync(0xFFFFFFFFu, s1, o);
        s2 += __shfl_xor_sync(0xFFFFFFFFu, s2, o);
    }
    mean = s1 * (1.f / 256.f);
    var  = s2 * (1.f / 256.f) - mean * mean;
}

// LN + roll + window-partition; warp-per-token (8 tokens/block), fp16 out
__global__ __launch_bounds__(256)
void ln_winpart_k(const float* __restrict__ h, const float* __restrict__ g,
                  const float* __restrict__ be, __half* __restrict__ out,
                  int shift) {
    int warp = threadIdx.x >> 5, lane = threadIdx.x & 31;
    int wt = blockIdx.x * 8 + warp;          // window-token index
    int srow = decomp_win(wt, shift);
    int c0 = lane * 8;
    float v[8];
    *(float4*)(v)     = *(const float4*)&h[(size_t)srow * CH + c0];
    *(float4*)(v + 4) = *(const float4*)&h[(size_t)srow * CH + c0 + 4];
    float mean, var;
    warp_stats(v, mean, var);
    float rstd = rsqrtf(var + 1e-5f);
    __half hv[8];
#pragma unroll
    for (int i = 0; i < 8; i++)
        hv[i] = __float2half_rn((v[i] - mean) * rstd * g[c0 + i] + be[c0 + i]);
    *(float4*)&out[(size_t)wt * CH + c0] = *(float4*)hv;
}

// Plain LN (token order); warp-per-token; fp16 out
__global__ __launch_bounds__(256)
void ln_plain_k(const float* __restrict__ h, const float* __restrict__ g,
                const float* __restrict__ be, __half* __restrict__ out) {
    int warp = threadIdx.x >> 5, lane = threadIdx.x & 31;
    int wt = blockIdx.x * 8 + warp;
    int c0 = lane * 8;
    float v[8];
    *(float4*)(v)     = *(const float4*)&h[(size_t)wt * CH + c0];
    *(float4*)(v + 4) = *(const float4*)&h[(size_t)wt * CH + c0 + 4];
    float mean, var;
    warp_stats(v, mean, var);
    float rstd = rsqrtf(var + 1e-5f);
    __half hv[8];
#pragma unroll
    for (int i = 0; i < 8; i++)
        hv[i] = __float2half_rn((v[i] - mean) * rstd * g[c0 + i] + be[c0 + i]);
    *(float4*)&out[(size_t)wt * CH + c0] = *(float4*)hv;
}

// ---------------------------------------------------------------------------
// Attention bias+mask table
// ---------------------------------------------------------------------------
__device__ __forceinline__ int axlab(int border, int i) {
    return border ? (i >= 2 ? 2 : 1) : 0;
}

__global__ void attn_tab_k(const float* __restrict__ rpb, float* __restrict__ tab,
                           int shift) {
    int cls = blockIdx.x >> 3, head = blockIdx.x & 7;
    int r = threadIdx.x;
    int bh = (cls >> 2) & 1, bw = (cls >> 1) & 1, bt = cls & 1;
    int ri = r >> 4, rj = (r >> 2) & 3, rk = r & 3;
    int labr = axlab(bh, ri) * 9 + axlab(bw, rj) * 3 + axlab(bt, rk);
    float* dst = tab + ((size_t)(cls * 8 + head) * 64 + r) * 64;
    for (int m = 0; m < 64; m++) {
        int mi = m >> 4, mj = (m >> 2) & 3, mk = m & 3;
        float v = rpb[((ri - mi + 3) * 49 + (rj - mj + 3) * 7 + (rk - mk + 3)) * 8 + head];
        if (shift) {
            int labm = axlab(bh, mi) * 9 + axlab(bw, mj) * 3 + axlab(bt, mk);
            if (labm != labr) v -= 100.f;
        }
        dst[m] = v;
    }
}

// ---------------------------------------------------------------------------
// Tensor-core windowed attention: one WARP per (window, head).
// ---------------------------------------------------------------------------
__device__ __forceinline__ void mma16816a(float* d, uint32_t a0, uint32_t a1,
                                          uint32_t a2, uint32_t a3,
                                          uint32_t b0, uint32_t b1) {
    asm volatile(
        "mma.sync.aligned.m16n8k16.row.col.f32.f16.f16.f32 "
        "{%0,%1,%2,%3},{%4,%5,%6,%7},{%8,%9},{%0,%1,%2,%3};"
        : "+f"(d[0]), "+f"(d[1]), "+f"(d[2]), "+f"(d[3])
        : "r"(a0), "r"(a1), "r"(a2), "r"(a3), "r"(b0), "r"(b1));
}
__device__ __forceinline__ uint32_t h2u(__half2 h) { return *(uint32_t*)&h; }

__global__ __launch_bounds__(128)
void attn_k(const __half* __restrict__ qkv, const float* __restrict__ tab,
            __half* __restrict__ o, int shift) {
    int widx = blockIdx.x >> 1;
    int head = (blockIdx.x & 1) * 4 + (threadIdx.x >> 5);
    int lane = threadIdx.x & 31;
    int g = lane >> 2, cc = lane & 3;

    const __half* base = qkv + (size_t)widx * 64 * 768;
    const __half* Q = base + head * 32;
    const __half* K = base + 256 + head * 32;
    const __half* V = base + 512 + head * 32;

    int cls = 0;
    if (shift) {
        int wr = widx & 511;
        cls = (((wr >> 6) == 7) << 2) | ((((wr >> 3) & 7) == 7) << 1) | ((wr & 7) == 7);
    }
    const float* T = tab + (size_t)(cls * 8 + head) * 4096;

    // ---- S = Q K^T  (64x64x32) ----
    float S[4][8][4];
#pragma unroll
    for (int i = 0; i < 4; i++)
#pragma unroll
        for (int j = 0; j < 8; j++)
#pragma unroll
            for (int c = 0; c < 4; c++) S[i][j][c] = 0.f;

#pragma unroll
    for (int t = 0; t < 2; t++) {
        uint32_t a[4][4];
#pragma unroll
        for (int i = 0; i < 4; i++) {
            const __half* q0 = Q + (size_t)(16 * i + g) * 768 + t * 16 + 2 * cc;
            a[i][0] = *(const uint32_t*)(q0);
            a[i][1] = *(const uint32_t*)(q0 + 8 * 768);
            a[i][2] = *(const uint32_t*)(q0 + 8);
            a[i][3] = *(const uint32_t*)(q0 + 8 * 768 + 8);
        }
        uint32_t bq[8][2];
#pragma unroll
        for (int j = 0; j < 8; j++) {
            const __half* k0 = K + (size_t)(8 * j + g) * 768 + t * 16 + 2 * cc;
            bq[j][0] = *(const uint32_t*)(k0);
            bq[j][1] = *(const uint32_t*)(k0 + 8);
        }
#pragma unroll
        for (int i = 0; i < 4; i++)
#pragma unroll
            for (int j = 0; j < 8; j++)
                mma16816a(S[i][j], a[i][0], a[i][1], a[i][2], a[i][3],
                          bq[j][0], bq[j][1]);
    }

    // ---- scale + bias ----
    const float sc = 0.17677669529663687f;
#pragma unroll
    for (int i = 0; i < 4; i++)
#pragma unroll
        for (int j = 0; j < 8; j++) {
            float2 t0 = *(const float2*)&T[(16 * i + g) * 64 + 8 * j + 2 * cc];
            float2 t1 = *(const float2*)&T[(16 * i + g + 8) * 64 + 8 * j + 2 * cc];
            S[i][j][0] = S[i][j][0] * sc + t0.x;
            S[i][j][1] = S[i][j][1] * sc + t0.y;
            S[i][j][2] = S[i][j][2] * sc + t1.x;
            S[i][j][3] = S[i][j][3] * sc + t1.y;
        }

    // ---- softmax ----
    float inv0[4], inv1[4];
#pragma unroll
    for (int i = 0; i < 4; i++) {
        float m0 = -1e30f, m1 = -1e30f;
#pragma unroll
        for (int j = 0; j < 8; j++) {
            m0 = fmaxf(m0, fmaxf(S[i][j][0], S[i][j][1]));
            m1 = fmaxf(m1, fmaxf(S[i][j][2], S[i][j][3]));
        }
        m0 = fmaxf(m0, __shfl_xor_sync(0xFFFFFFFFu, m0, 1));
        m0 = fmaxf(m0, __shfl_xor_sync(0xFFFFFFFFu, m0, 2));
        m1 = fmaxf(m1, __shfl_xor_sync(0xFFFFFFFFu, m1, 1));
        m1 = fmaxf(m1, __shfl_xor_sync(0xFFFFFFFFu, m1, 2));
        float s0 = 0.f, s1 = 0.f;
#pragma unroll
        for (int j = 0; j < 8; j++) {
            float e0 = __expf(S[i][j][0] - m0);
            float e1 = __expf(S[i][j][1] - m0);
            float e2 = __expf(S[i][j][2] - m1);
            float e3 = __expf(S[i][j][3] - m1);
            S[i][j][0] = e0; S[i][j][1] = e1; S[i][j][2] = e2; S[i][j][3] = e3;
            s0 += e0 + e1; s1 += e2 + e3;
        }
        s0 += __shfl_xor_sync(0xFFFFFFFFu, s0, 1);
        s0 += __shfl_xor_sync(0xFFFFFFFFu, s0, 2);
        s1 += __shfl_xor_sync(0xFFFFFFFFu, s1, 1);
        s1 += __shfl_xor_sync(0xFFFFFFFFu, s1, 2);
        inv0[i] = 1.f / s0;
        inv1[i] = 1.f / s1;
    }

    // ---- scores -> fp16 A fragments ----
    uint32_t Sh[4][8][2];
#pragma unroll
    for (int i = 0; i < 4; i++)
#pragma unroll
        for (int j = 0; j < 8; j++) {
            Sh[i][j][0] = h2u(__floats2half2_rn(S[i][j][0], S[i][j][1]));
            Sh[i][j][1] = h2u(__floats2half2_rn(S[i][j][2], S[i][j][3]));
        }

    // ---- O = S V  (64x32x64) ----
    float O[4][4][4];
#pragma unroll
    for (int i = 0; i < 4; i++)
#pragma unroll
        for (int j = 0; j < 4; j++)
#pragma unroll
            for (int c = 0; c < 4; c++) O[i][j][c] = 0.f;

#pragma unroll
    for (int t = 0; t < 4; t++) {
        uint32_t bv[4][2];
#pragma unroll
        for (int j = 0; j < 4; j++) {
            const __half* v0 = V + (size_t)(16 * t + 2 * cc) * 768 + 8 * j + g;
            bv[j][0] = h2u(__halves2half2(v0[0], v0[768]));
            bv[j][1] = h2u(__halves2half2(v0[8 * 768], v0[9 * 768]));
        }
#pragma unroll
        for (int i = 0; i < 4; i++)
#pragma unroll
            for (int j = 0; j < 4; j++)
                mma16816a(O[i][j], Sh[i][2 * t][0], Sh[i][2 * t][1],
                          Sh[i][2 * t + 1][0], Sh[i][2 * t + 1][1],
                          bv[j][0], bv[j][1]);
    }

    // ---- write out ----
    __half* ob = o + (size_t)widx * 64 * CH + head * 32;
#pragma unroll
    for (int i = 0; i < 4; i++) {
        int r0 = 16 * i + g;
#pragma unroll
        for (int j = 0; j < 4; j++) {
            int col = 8 * j + 2 * cc;
            *(__half2*)(ob + (size_t)r0 * CH + col) =
                __floats2half2_rn(O[i][j][0] * inv0[i], O[i][j][1] * inv0[i]);
            *(__half2*)(ob + (size_t)(r0 + 8) * CH + col) =
                __floats2half2_rn(O[i][j][2] * inv1[i], O[i][j][3] * inv1[i]);
        }
    }
}

// ---------------------------------------------------------------------------
// FP16 tensor-core GEMM: mma.sync.m16n8k16, ldmatrix fragments.
// R12 config: block tile 128x128, 8 warps (2x4), warp tile 64x32, K-tile 32,
// TWO-stage cp.async issue-before-wait, 2 CTAs/SM. RSTR=40 pad.
// EPI: 0 bias, 1 bias+GELU, 2 bias+residual, 3 bias+ReLU,
//      4 bias + window-reverse residual accumulate into h (fp32, row->srow).
// OHALF: fp16 out.
// ---------------------------------------------------------------------------
#define RSTR 40                           // halves per smem row
#define ASTAGE (128 * RSTR)               // halves
#define BSTAGE (128 * RSTR)
#define HG_SMEM ((2 * ASTAGE + 2 * BSTAGE) * 2)   // 40960 bytes

__device__ __forceinline__ uint32_t smem_u32(const void* p) {
    uint32_t a;
    asm("{ .reg .u64 t; cvta.to.shared.u64 t, %1; cvt.u32.u64 %0, t; }" : "=r"(a) : "l"(p));
    return a;
}
__device__ __forceinline__ void cp16(uint32_t dst, const void* src) {
    asm volatile("cp.async.cg.shared.global [%0], [%1], 16;\n" :: "r"(dst), "l"(src));
}
__device__ __forceinline__ void ldm4(uint32_t* f, uint32_t a) {
    asm volatile("ldmatrix.sync.aligned.m8n8.x4.shared.b16 {%0,%1,%2,%3}, [%4];"
                 : "=r"(f[0]), "=r"(f[1]), "=r"(f[2]), "=r"(f[3]) : "r"(a));
}
__device__ __forceinline__ void mma16816(float* d, const uint32_t* a, uint32_t b0, uint32_t b1) {
    asm volatile(
        "mma.sync.aligned.m16n8k16.row.col.f32.f16.f16.f32 "
        "{%0,%1,%2,%3},{%4,%5,%6,%7},{%8,%9},{%0,%1,%2,%3};"
        : "+f"(d[0]), "+f"(d[1]), "+f"(d[2]), "+f"(d[3])
        : "r"(a[0]), "r"(a[1]), "r"(a[2]), "r"(a[3]), "r"(b0), "r"(b1));
}

template <int EPI, int OHALF>
__global__ __launch_bounds__(256, 2)
void hgemm_k(const __half* __restrict__ A, const __half* __restrict__ Bw,
             const float* __restrict__ bias, float* __restrict__ res,
             float* __restrict__ C, __half* __restrict__ C16,
             int M, int N, int K, int shiftp) {
    extern __shared__ __half sh[];
    uint32_t sA[2], sB[2];
    sA[0] = smem_u32(sh);
    sA[1] = sA[0] + ASTAGE * 2;
    sB[0] = sA[1] + ASTAGE * 2;
    sB[1] = sB[0] + BSTAGE * 2;

    int tid = threadIdx.x, lane = tid & 31, warp = tid >> 5;
    int wm = (warp & 1) * 64, wn = (warp >> 1) * 32;
    int bm = blockIdx.y * 128, bn = blockIdx.x * 128;

    uint32_t aoff = (uint32_t)(lane & 15) * (RSTR * 2) + ((lane >> 4) & 1) * 16;
    uint32_t boff = (uint32_t)((lane & 7) + ((lane >> 4) & 1) * 8) * (RSTR * 2)
                  + ((lane >> 3) & 1) * 16;

    int arow = tid >> 1, ach = (tid & 1) * 2;
    const __half* Ag = A + (size_t)(bm + arow) * K + ach * 8;
    const __half* Bg = Bw + (size_t)(bn + arow) * K + ach * 8;
    uint32_t adst = (uint32_t)arow * (RSTR * 2) + ach * 16;

    float acc[4][4][4];
#pragma unroll
    for (int i = 0; i < 4; i++)
#pragma unroll
        for (int j = 0; j < 4; j++)
#pragma unroll
            for (int c2 = 0; c2 < 4; c2++) acc[i][j][c2] = 0.f;

    int nkt = K >> 5;

    cp16(sA[0] + adst,      Ag);
    cp16(sA[0] + adst + 16, Ag + 8);
    cp16(sB[0] + adst,      Bg);
    cp16(sB[0] + adst + 16, Bg + 8);
    asm volatile("cp.async.commit_group;\n");

    int buf = 0;
    for (int kt = 0; kt < nkt; kt++) {
        if (kt + 1 < nkt) {
            int ko = (kt + 1) * 32;
            uint32_t da = sA[buf ^ 1], db = sB[buf ^ 1];
            cp16(da + adst,      Ag + ko);
            cp16(da + adst + 16, Ag + ko + 8);
            cp16(db + adst,      Bg + ko);
            cp16(db + adst + 16, Bg + ko + 8);
            asm volatile("cp.async.commit_group;\n");
            asm volatile("cp.async.wait_group 1;\n");
        } else {
            asm volatile("cp.async.wait_group 0;\n");
        }
        __syncthreads();

        uint32_t sa = sA[buf], sbb = sB[buf];
#pragma unroll
        for (int kk = 0; kk < 2; kk++) {
            uint32_t af[4][4], bf[2][4];
#pragma unroll
            for (int im = 0; im < 4; im++)
                ldm4(af[im], sa + (uint32_t)(wm + im * 16) * (RSTR * 2) + kk * 32 + aoff);
#pragma unroll
            for (int jn = 0; jn < 2; jn++)
                ldm4(bf[jn], sbb + (uint32_t)(wn + jn * 16) * (RSTR * 2) + kk * 32 + boff);
#pragma unroll
            for (int im = 0; im < 4; im++)
#pragma unroll
                for (int jn = 0; jn < 2; jn++) {
                    mma16816(acc[im][jn * 2],     af[im], bf[jn][0], bf[jn][1]);
                    mma16816(acc[im][jn * 2 + 1], af[im], bf[jn][2], bf[jn][3]);
                }
        }
        __syncthreads();
        buf ^= 1;
    }

    int g = lane >> 2, cc = lane & 3;
#pragma unroll
    for (int im = 0; im < 4; im++) {
        int row0 = bm + wm + im * 16 + g;
        int orow0 = row0, orow1 = row0 + 8;
        if (EPI == 4) {
            orow0 = decomp_win(row0, shiftp);
            orow1 = decomp_win(row0 + 8, shiftp);
        }
#pragma unroll
        for (int j = 0; j < 4; j++) {
            int col = bn + wn + j * 8 + cc * 2;
            float b0 = bias[col], b1 = bias[col + 1];
            float v0 = acc[im][j][0] + b0, v1 = acc[im][j][1] + b1;
            float v2 = acc[im][j][2] + b0, v3 = acc[im][j][3] + b1;
            if (EPI == 1) {
                v0 = 0.5f * v0 * (1.f + erff(v0 * 0.70710678118654752f));
                v1 = 0.5f * v1 * (1.f + erff(v1 * 0.70710678118654752f));
                v2 = 0.5f * v2 * (1.f + erff(v2 * 0.70710678118654752f));
                v3 = 0.5f * v3 * (1.f + erff(v3 * 0.70710678118654752f));
            }
            if (EPI == 2 || EPI == 4) {
                float2 r0v = *(const float2*)&res[(size_t)orow0 * N + col];
                float2 r1v = *(const float2*)&res[(size_t)orow1 * N + col];
                v0 += r0v.x; v1 += r0v.y; v2 += r1v.x; v3 += r1v.y;
            }
            if (EPI == 3) {
                v0 = fmaxf(v0, 0.f); v1 = fmaxf(v1, 0.f);
                v2 = fmaxf(v2, 0.f); v3 = fmaxf(v3, 0.f);
            }
            if (OHALF) {
                *(__half2*)&C16[(size_t)orow0 * N + col] = __floats2half2_rn(v0, v1);
                *(__half2*)&C16[(size_t)orow1 * N + col] = __floats2half2_rn(v2, v3);
            } else {
                float2 o0; o0.x = v0; o0.y = v1;
                float2 o1; o1.x = v2; o1.y = v3;
                *(float2*)&C[(size_t)orow0 * N + col] = o0;
                *(float2*)&C[(size_t)orow1 * N + col] = o1;
            }
        }
    }
}

// ---------------------------------------------------------------------------
// Depthwise 3x3x3 conv, channels-last; fp16 out
// ---------------------------------------------------------------------------
__global__ __launch_bounds__(256)
void dwconv_k(const float* __restrict__ in, const float* __restrict__ w,
              __half* __restrict__ out) {
    __shared__ float ws[256 * 27];
    int tid = threadIdx.x;
    for (int idx = tid; idx < 256 * 27; idx += 256) ws[idx] = w[idx];
    __syncthreads();
    int bx = blockIdx.x;
    int tc = bx & 3;  bx >>= 2;
    int wp = bx & 31; bx >>= 5;
    int hp = bx & 31; bx >>= 5;
    int b  = bx;
    int c  = tid;
    const float* ib = in  + (size_t)b * L * CH;
    __half*      ob = out + (size_t)b * L * CH;
#pragma unroll
    for (int tt = 0; tt < 8; tt++) {
        int t = tc * 8 + tt;
        float acc = 0.f;
#pragma unroll
        for (int dh = -1; dh <= 1; dh++) {
            int h2 = hp + dh; if (h2 < 0 || h2 > 31) continue;
#pragma unroll
            for (int dw = -1; dw <= 1; dw++) {
                int w2 = wp + dw; if (w2 < 0 || w2 > 31) continue;
#pragma unroll
                for (int dt = -1; dt <= 1; dt++) {
                    int t2 = t + dt; if (t2 < 0 || t2 > 31) continue;
                    acc += ws[c * 27 + (dh + 1) * 9 + (dw + 1) * 3 + (dt + 1)] *
                           ib[(size_t)(h2 * 1024 + w2 * 32 + t2) * CH + c];
                }
            }
        }
        ob[(size_t)(hp * 1024 + wp * 32 + t) * CH + c] = __float2half_rn(acc);
    }
}

// ---------------------------------------------------------------------------
// Launch
// ---------------------------------------------------------------------------
extern "C" void kernel_launch(void* const* d_in, const int* in_sizes, int n_in,
                              void* d_out, int out_size) {
    const float* x      = (const float*)d_in[0];
    const float* g1     = (const float*)d_in[1];
    const float* b1     = (const float*)d_in[2];
    const float* qkv_w  = (const float*)d_in[3];
    const float* qkv_b  = (const float*)d_in[4];
    const float* proj_w = (const float*)d_in[5];
    const float* proj_b = (const float*)d_in[6];
    const float* rpb    = (const float*)d_in[7];
    const float* g2     = (const float*)d_in[8];
    const float* b2     = (const float*)d_in[9];
    const float* fc1_w  = (const float*)d_in[10];
    const float* fc1_b  = (const float*)d_in[11];
    const float* fc2_w  = (const float*)d_in[12];
    const float* fc2_b  = (const float*)d_in[13];
    const float* dw_w   = (const float*)d_in[14];
    const float* pw_w   = (const float*)d_in[15];
    const float* pw_b   = (const float*)d_in[16];
    float* out = (float*)d_out;

    float *ph, *ptab;
    __half *hwin, *hqkv, *hmid, *hwts, *hpwT;
    cudaGetSymbolAddress((void**)&ph,   g_h);
    cudaGetSymbolAddress((void**)&hwin, g_win);
    cudaGetSymbolAddress((void**)&hqkv, g_qkv);
    cudaGetSymbolAddress((void**)&hmid, g_mid);
    cudaGetSymbolAddress((void**)&hwts, g_wts);
    cudaGetSymbolAddress((void**)&hpwT, g_pwT);
    cudaGetSymbolAddress((void**)&ptab, g_tab);
    float* fscratch = (float*)hqkv;   // fp32 view for pw output

    // weight prepass: [K][N] -> [N][K] fp16
    wtransH_k<<<dim3(8, 24, 4), dim3(32, 8)>>>(qkv_w,  hwts + W_QKV,  256, 768);
    wtransH_k<<<dim3(8, 8, 4),  dim3(32, 8)>>>(proj_w, hwts + W_PROJ, 256, 256);
    wtransH_k<<<dim3(8, 32, 4), dim3(32, 8)>>>(fc1_w,  hwts + W_FC1,  256, 1024);
    wtransH_k<<<dim3(32, 8, 4), dim3(32, 8)>>>(fc2_w,  hwts + W_FC2,  1024, 256);
    cvt_k<<<256, 256>>>(pw_w, hpwT, 65536);       // [co][ci] already [N][K]

    // x [b][c][p] -> h [b][p][c]
    transpose_k<<<dim3(8, 1024, 2), dim3(32, 8)>>>(x, ph, 256, 32768);

    for (int blk = 0; blk < 4; blk++) {
        int shift = (blk & 1) ? 2 : 0;
        ln_winpart_k<<<MROWS / 8, 256>>>(ph, g1 + blk * 256, b1 + blk * 256, hwin, shift);
        hgemm_k<0, 1><<<dim3(6, 512), 256, HG_SMEM>>>(
            hwin, hwts + W_QKV + (size_t)blk * 256 * 768, qkv_b + blk * 768, nullptr,
            nullptr, hqkv, MROWS, 768, 256, 0);
        attn_tab_k<<<64, 64>>>(rpb + blk * 343 * 8, ptab, shift);
        attn_k<<<TOTW * 2, 128>>>(hqkv, ptab, hwin, shift);
        // proj GEMM + fused window-reverse residual accumulate into h
        hgemm_k<4, 0><<<dim3(2, 512), 256, HG_SMEM>>>(
            hwin, hwts + W_PROJ + (size_t)blk * 256 * 256, proj_b + blk * 256, ph,
            ph, nullptr, MROWS, 256, 256, shift);
        ln_plain_k<<<MROWS / 8, 256>>>(ph, g2 + blk * 256, b2 + blk * 256, hwin);
        hgemm_k<1, 1><<<dim3(8, 512), 256, HG_SMEM>>>(
            hwin, hwts + W_FC1 + (size_t)blk * 256 * 1024, fc1_b + blk * 1024, nullptr,
            nullptr, hmid, MROWS, 1024, 256, 0);
        hgemm_k<2, 0><<<dim3(2, 512), 256, HG_SMEM>>>(
            hmid, hwts + W_FC2 + (size_t)blk * 1024 * 256, fc2_b + blk * 256, ph,
            ph, nullptr, MROWS, 256, 1024, 0);
    }

    dwconv_k<<<BATCH * 32 * 32 * 4, 256>>>(ph, dw_w, hwin);
    hgemm_k<3, 0><<<dim3(2, 512), 256, HG_SMEM>>>(
        hwin, hpwT, pw_b, nullptr, fscratch, nullptr, MROWS, 256, 256, 0);
    transpose_k<<<dim3(1024, 8, 2), dim3(32, 8)>>>(fscratch, out, 32768, 256);
}

// round 17
// speedup vs baseline: 1.1686x; 1.0185x over previous
#include <cuda_runtime.h>
#include <cuda_fp16.h>
#include <math.h>
#include <stdint.h>

// ---------------------------------------------------------------------------
// Problem constants
// ---------------------------------------------------------------------------
#define BATCH 2
#define CH    256
#define L     32768
#define NH    8
#define TOTW  1024
#define MROWS 65536

// ---------------------------------------------------------------------------
// Scratch (device globals; allocation-free)
// ---------------------------------------------------------------------------
__device__ float  g_h[(size_t)BATCH * L * CH];      // residual stream fp32 [b][p][c]
__device__ __half g_win[(size_t)MROWS * CH];        // fp16 activations (GEMM A)
__device__ __half g_qkv[(size_t)MROWS * 768];       // fp16 qkv; also fp32-view scratch
__device__ __half g_mid[(size_t)MROWS * 1024];      // fp16 MLP hidden
__device__ __half g_wts[3145728];                   // fp16 weights, [N][K]
__device__ __half g_pwT[CH * CH];                   // fp16 pointwise W [co][ci]=[N][K]
__device__ float  g_tab[8 * 8 * 64 * 64];           // attn bias+mask table

#define W_QKV 0
#define W_PROJ 786432
#define W_FC1 1048576
#define W_FC2 2097152

// Fast GELU (tanh form, __expf-based); |err| vs exact erf-GELU ~3e-4 abs.
__device__ __forceinline__ float fast_gelu(float v) {
    float u = 1.5957691216057308f * (v + 0.044715f * v * v * v);  // 2*0.79788456*(...)
    float t = 1.f - __fdividef(2.f, __expf(u) + 1.f);             // tanh(u/... )
    return 0.5f * v * (1.f + t);
}

// ---------------------------------------------------------------------------
// Batched 2D transpose (fp32, for harness I/O layout)
// ---------------------------------------------------------------------------
__global__ void transpose_k(const float* __restrict__ in, float* __restrict__ out,
                            int R, int Cc) {
    __shared__ float tile[32][33];
    int b  = blockIdx.z;
    int r0 = blockIdx.x * 32, c0 = blockIdx.y * 32;
    const float* ib = in  + (size_t)b * R * Cc;
    float*       ob = out + (size_t)b * R * Cc;
    int tx = threadIdx.x, ty = threadIdx.y;
#pragma unroll
    for (int i = 0; i < 4; i++)
        tile[ty + i * 8][tx] = ib[(size_t)(r0 + ty + i * 8) * Cc + c0 + tx];
    __syncthreads();
#pragma unroll
    for (int i = 0; i < 4; i++)
        ob[(size_t)(c0 + ty + i * 8) * R + r0 + tx] = tile[tx][ty + i * 8];
}

// Transpose + fp16-convert weights: [R][C] -> [C][R], batched over z
__global__ void wtransH_k(const float* __restrict__ in, __half* __restrict__ out,
                          int R, int Cc) {
    __shared__ float tile[32][33];
    int b  = blockIdx.z;
    int r0 = blockIdx.x * 32, c0 = blockIdx.y * 32;
    const float* ib = in  + (size_t)b * R * Cc;
    __half*      ob = out + (size_t)b * R * Cc;
    int tx = threadIdx.x, ty = threadIdx.y;
#pragma unroll
    for (int i = 0; i < 4; i++)
        tile[ty + i * 8][tx] = ib[(size_t)(r0 + ty + i * 8) * Cc + c0 + tx];
    __syncthreads();
#pragma unroll
    for (int i = 0; i < 4; i++)
        ob[(size_t)(c0 + ty + i * 8) * R + r0 + tx] = __float2half_rn(tile[tx][ty + i * 8]);
}

// Convert only (fp32 -> fp16)
__global__ void cvt_k(const float* __restrict__ src, __half* __restrict__ dst, int n) {
    int i = blockIdx.x * 256 + threadIdx.x;
    if (i < n) dst[i] = __float2half_rn(src[i]);
}

// ---------------------------------------------------------------------------
// Window-token index -> source row (fused roll)
// ---------------------------------------------------------------------------
__device__ __forceinline__ int decomp_win(int wt_idx, int shift) {
    int widx = wt_idx >> 6, n = wt_idx & 63;
    int b = widx >> 9;  int wr = widx & 511;
    int wh = wr >> 6, ww = (wr >> 3) & 7, wt = wr & 7;
    int i = n >> 4, j = (n >> 2) & 3, k = n & 3;
    int gh = (wh * 4 + i + shift) & 31;
    int gw = (ww * 4 + j + shift) & 31;
    int gt = (wt * 4 + k + shift) & 31;
    return b * L + gh * 1024 + gw * 32 + gt;
}

// Warp-level mean/var of 8 values per lane (256 channels per warp).
__device__ __forceinline__ void warp_stats(const float* v, float& mean, float& var) {
    float s1 = 0.f, s2 = 0.f;
#pragma unroll
    for (int i = 0; i < 8; i++) { s1 += v[i]; s2 += v[i] * v[i]; }
#pragma unroll
    for (int o = 16; o > 0; o >>= 1) {
        s1 += __shfl_xor_sync(0xFFFFFFFFu, s1, o);
        s2 += __shfl_xor_sync(0xFFFFFFFFu, s2, o);
    }
    mean = s1 * (1.f / 256.f);
    var  = s2 * (1.f / 256.f) - mean * mean;
}

// LN + roll + window-partition; warp-per-token (8 tokens/block), fp16 out
__global__ __launch_bounds__(256)
void ln_winpart_k(const float* __restrict__ h, const float* __restrict__ g,
                  const float* __restrict__ be, __half* __restrict__ out,
                  int shift) {
    int warp = threadIdx.x >> 5, lane = threadIdx.x & 31;
    int wt = blockIdx.x * 8 + warp;          // window-token index
    int srow = decomp_win(wt, shift);
    int c0 = lane * 8;
    float v[8];
    *(float4*)(v)     = *(const float4*)&h[(size_t)srow * CH + c0];
    *(float4*)(v + 4) = *(const float4*)&h[(size_t)srow * CH + c0 + 4];
    float mean, var;
    warp_stats(v, mean, var);
    float rstd = rsqrtf(var + 1e-5f);
    __half hv[8];
#pragma unroll
    for (int i = 0; i < 8; i++)
        hv[i] = __float2half_rn((v[i] - mean) * rstd * g[c0 + i] + be[c0 + i]);
    *(float4*)&out[(size_t)wt * CH + c0] = *(float4*)hv;
}

// Plain LN (token order); warp-per-token; fp16 out
__global__ __launch_bounds__(256)
void ln_plain_k(const float* __restrict__ h, const float* __restrict__ g,
                const float* __restrict__ be, __half* __restrict__ out) {
    int warp = threadIdx.x >> 5, lane = threadIdx.x & 31;
    int wt = blockIdx.x * 8 + warp;
    int c0 = lane * 8;
    float v[8];
    *(float4*)(v)     = *(const float4*)&h[(size_t)wt * CH + c0];
    *(float4*)(v + 4) = *(const float4*)&h[(size_t)wt * CH + c0 + 4];
    float mean, var;
    warp_stats(v, mean, var);
    float rstd = rsqrtf(var + 1e-5f);
    __half hv[8];
#pragma unroll
    for (int i = 0; i < 8; i++)
        hv[i] = __float2half_rn((v[i] - mean) * rstd * g[c0 + i] + be[c0 + i]);
    *(float4*)&out[(size_t)wt * CH + c0] = *(float4*)hv;
}

// ---------------------------------------------------------------------------
// Attention bias+mask table
// ---------------------------------------------------------------------------
__device__ __forceinline__ int axlab(int border, int i) {
    return border ? (i >= 2 ? 2 : 1) : 0;
}

__global__ void attn_tab_k(const float* __restrict__ rpb, float* __restrict__ tab,
                           int shift) {
    int cls = blockIdx.x >> 3, head = blockIdx.x & 7;
    int r = threadIdx.x;
    int bh = (cls >> 2) & 1, bw = (cls >> 1) & 1, bt = cls & 1;
    int ri = r >> 4, rj = (r >> 2) & 3, rk = r & 3;
    int labr = axlab(bh, ri) * 9 + axlab(bw, rj) * 3 + axlab(bt, rk);
    float* dst = tab + ((size_t)(cls * 8 + head) * 64 + r) * 64;
    for (int m = 0; m < 64; m++) {
        int mi = m >> 4, mj = (m >> 2) & 3, mk = m & 3;
        float v = rpb[((ri - mi + 3) * 49 + (rj - mj + 3) * 7 + (rk - mk + 3)) * 8 + head];
        if (shift) {
            int labm = axlab(bh, mi) * 9 + axlab(bw, mj) * 3 + axlab(bt, mk);
            if (labm != labr) v -= 100.f;
        }
        dst[m] = v;
    }
}

// ---------------------------------------------------------------------------
// Tensor-core windowed attention: one WARP per (window, head).
// ---------------------------------------------------------------------------
__device__ __forceinline__ void mma16816a(float* d, uint32_t a0, uint32_t a1,
                                          uint32_t a2, uint32_t a3,
                                          uint32_t b0, uint32_t b1) {
    asm volatile(
        "mma.sync.aligned.m16n8k16.row.col.f32.f16.f16.f32 "
        "{%0,%1,%2,%3},{%4,%5,%6,%7},{%8,%9},{%0,%1,%2,%3};"
        : "+f"(d[0]), "+f"(d[1]), "+f"(d[2]), "+f"(d[3])
        : "r"(a0), "r"(a1), "r"(a2), "r"(a3), "r"(b0), "r"(b1));
}
__device__ __forceinline__ uint32_t h2u(__half2 h) { return *(uint32_t*)&h; }

__global__ __launch_bounds__(128)
void attn_k(const __half* __restrict__ qkv, const float* __restrict__ tab,
            __half* __restrict__ o, int shift) {
    int widx = blockIdx.x >> 1;
    int head = (blockIdx.x & 1) * 4 + (threadIdx.x >> 5);
    int lane = threadIdx.x & 31;
    int g = lane >> 2, cc = lane & 3;

    const __half* base = qkv + (size_t)widx * 64 * 768;
    const __half* Q = base + head * 32;
    const __half* K = base + 256 + head * 32;
    const __half* V = base + 512 + head * 32;

    int cls = 0;
    if (shift) {
        int wr = widx & 511;
        cls = (((wr >> 6) == 7) << 2) | ((((wr >> 3) & 7) == 7) << 1) | ((wr & 7) == 7);
    }
    const float* T = tab + (size_t)(cls * 8 + head) * 4096;

    // ---- S = Q K^T  (64x64x32) ----
    float S[4][8][4];
#pragma unroll
    for (int i = 0; i < 4; i++)
#pragma unroll
        for (int j = 0; j < 8; j++)
#pragma unroll
            for (int c = 0; c < 4; c++) S[i][j][c] = 0.f;

#pragma unroll
    for (int t = 0; t < 2; t++) {
        uint32_t a[4][4];
#pragma unroll
        for (int i = 0; i < 4; i++) {
            const __half* q0 = Q + (size_t)(16 * i + g) * 768 + t * 16 + 2 * cc;
            a[i][0] = *(const uint32_t*)(q0);
            a[i][1] = *(const uint32_t*)(q0 + 8 * 768);
            a[i][2] = *(const uint32_t*)(q0 + 8);
            a[i][3] = *(const uint32_t*)(q0 + 8 * 768 + 8);
        }
        uint32_t bq[8][2];
#pragma unroll
        for (int j = 0; j < 8; j++) {
            const __half* k0 = K + (size_t)(8 * j + g) * 768 + t * 16 + 2 * cc;
            bq[j][0] = *(const uint32_t*)(k0);
            bq[j][1] = *(const uint32_t*)(k0 + 8);
        }
#pragma unroll
        for (int i = 0; i < 4; i++)
#pragma unroll
            for (int j = 0; j < 8; j++)
                mma16816a(S[i][j], a[i][0], a[i][1], a[i][2], a[i][3],
                          bq[j][0], bq[j][1]);
    }

    // ---- scale + bias ----
    const float sc = 0.17677669529663687f;
#pragma unroll
    for (int i = 0; i < 4; i++)
#pragma unroll
        for (int j = 0; j < 8; j++) {
            float2 t0 = *(const float2*)&T[(16 * i + g) * 64 + 8 * j + 2 * cc];
            float2 t1 = *(const float2*)&T[(16 * i + g + 8) * 64 + 8 * j + 2 * cc];
            S[i][j][0] = S[i][j][0] * sc + t0.x;
            S[i][j][1] = S[i][j][1] * sc + t0.y;
            S[i][j][2] = S[i][j][2] * sc + t1.x;
            S[i][j][3] = S[i][j][3] * sc + t1.y;
        }

    // ---- softmax ----
    float inv0[4], inv1[4];
#pragma unroll
    for (int i = 0; i < 4; i++) {
        float m0 = -1e30f, m1 = -1e30f;
#pragma unroll
        for (int j = 0; j < 8; j++) {
            m0 = fmaxf(m0, fmaxf(S[i][j][0], S[i][j][1]));
            m1 = fmaxf(m1, fmaxf(S[i][j][2], S[i][j][3]));
        }
        m0 = fmaxf(m0, __shfl_xor_sync(0xFFFFFFFFu, m0, 1));
        m0 = fmaxf(m0, __shfl_xor_sync(0xFFFFFFFFu, m0, 2));
        m1 = fmaxf(m1, __shfl_xor_sync(0xFFFFFFFFu, m1, 1));
        m1 = fmaxf(m1, __shfl_xor_sync(0xFFFFFFFFu, m1, 2));
        float s0 = 0.f, s1 = 0.f;
#pragma unroll
        for (int j = 0; j < 8; j++) {
            float e0 = __expf(S[i][j][0] - m0);
            float e1 = __expf(S[i][j][1] - m0);
            float e2 = __expf(S[i][j][2] - m1);
            float e3 = __expf(S[i][j][3] - m1);
            S[i][j][0] = e0; S[i][j][1] = e1; S[i][j][2] = e2; S[i][j][3] = e3;
            s0 += e0 + e1; s1 += e2 + e3;
        }
        s0 += __shfl_xor_sync(0xFFFFFFFFu, s0, 1);
        s0 += __shfl_xor_sync(0xFFFFFFFFu, s0, 2);
        s1 += __shfl_xor_sync(0xFFFFFFFFu, s1, 1);
        s1 += __shfl_xor_sync(0xFFFFFFFFu, s1, 2);
        inv0[i] = 1.f / s0;
        inv1[i] = 1.f / s1;
    }

    // ---- scores -> fp16 A fragments ----
    uint32_t Sh[4][8][2];
#pragma unroll
    for (int i = 0; i < 4; i++)
#pragma unroll
        for (int j = 0; j < 8; j++) {
            Sh[i][j][0] = h2u(__floats2half2_rn(S[i][j][0], S[i][j][1]));
            Sh[i][j][1] = h2u(__floats2half2_rn(S[i][j][2], S[i][j][3]));
        }

    // ---- O = S V  (64x32x64) ----
    float O[4][4][4];
#pragma unroll
    for (int i = 0; i < 4; i++)
#pragma unroll
        for (int j = 0; j < 4; j++)
#pragma unroll
            for (int c = 0; c < 4; c++) O[i][j][c] = 0.f;

#pragma unroll
    for (int t = 0; t < 4; t++) {
        uint32_t bv[4][2];
#pragma unroll
        for (int j = 0; j < 4; j++) {
            const __half* v0 = V + (size_t)(16 * t + 2 * cc) * 768 + 8 * j + g;
            bv[j][0] = h2u(__halves2half2(v0[0], v0[768]));
            bv[j][1] = h2u(__halves2half2(v0[8 * 768], v0[9 * 768]));
        }
#pragma unroll
        for (int i = 0; i < 4; i++)
#pragma unroll
            for (int j = 0; j < 4; j++)
                mma16816a(O[i][j], Sh[i][2 * t][0], Sh[i][2 * t][1],
                          Sh[i][2 * t + 1][0], Sh[i][2 * t + 1][1],
                          bv[j][0], bv[j][1]);
    }

    // ---- write out ----
    __half* ob = o + (size_t)widx * 64 * CH + head * 32;
#pragma unroll
    for (int i = 0; i < 4; i++) {
        int r0 = 16 * i + g;
#pragma unroll
        for (int j = 0; j < 4; j++) {
            int col = 8 * j + 2 * cc;
            *(__half2*)(ob + (size_t)r0 * CH + col) =
                __floats2half2_rn(O[i][j][0] * inv0[i], O[i][j][1] * inv0[i]);
            *(__half2*)(ob + (size_t)(r0 + 8) * CH + col) =
                __floats2half2_rn(O[i][j][2] * inv1[i], O[i][j][3] * inv1[i]);
        }
    }
}

// ---------------------------------------------------------------------------
// FP16 tensor-core GEMM (R12 config). EPI: 0 bias, 1 bias+fastGELU,
// 2 bias+residual, 3 bias+ReLU, 4 bias+window-reverse residual into h.
// ---------------------------------------------------------------------------
#define RSTR 40                           // halves per smem row
#define ASTAGE (128 * RSTR)               // halves
#define BSTAGE (128 * RSTR)
#define HG_SMEM ((2 * ASTAGE + 2 * BSTAGE) * 2)   // 40960 bytes

__device__ __forceinline__ uint32_t smem_u32(const void* p) {
    uint32_t a;
    asm("{ .reg .u64 t; cvta.to.shared.u64 t, %1; cvt.u32.u64 %0, t; }" : "=r"(a) : "l"(p));
    return a;
}
__device__ __forceinline__ void cp16(uint32_t dst, const void* src) {
    asm volatile("cp.async.cg.shared.global [%0], [%1], 16;\n" :: "r"(dst), "l"(src));
}
__device__ __forceinline__ void ldm4(uint32_t* f, uint32_t a) {
    asm volatile("ldmatrix.sync.aligned.m8n8.x4.shared.b16 {%0,%1,%2,%3}, [%4];"
                 : "=r"(f[0]), "=r"(f[1]), "=r"(f[2]), "=r"(f[3]) : "r"(a));
}
__device__ __forceinline__ void mma16816(float* d, const uint32_t* a, uint32_t b0, uint32_t b1) {
    asm volatile(
        "mma.sync.aligned.m16n8k16.row.col.f32.f16.f16.f32 "
        "{%0,%1,%2,%3},{%4,%5,%6,%7},{%8,%9},{%0,%1,%2,%3};"
        : "+f"(d[0]), "+f"(d[1]), "+f"(d[2]), "+f"(d[3])
        : "r"(a[0]), "r"(a[1]), "r"(a[2]), "r"(a[3]), "r"(b0), "r"(b1));
}

template <int EPI, int OHALF>
__global__ __launch_bounds__(256, 2)
void hgemm_k(const __half* __restrict__ A, const __half* __restrict__ Bw,
             const float* __restrict__ bias, float* __restrict__ res,
             float* __restrict__ C, __half* __restrict__ C16,
             int M, int N, int K, int shiftp) {
    extern __shared__ __half sh[];
    uint32_t sA[2], sB[2];
    sA[0] = smem_u32(sh);
    sA[1] = sA[0] + ASTAGE * 2;
    sB[0] = sA[1] + ASTAGE * 2;
    sB[1] = sB[0] + BSTAGE * 2;

    int tid = threadIdx.x, lane = tid & 31, warp = tid >> 5;
    int wm = (warp & 1) * 64, wn = (warp >> 1) * 32;
    int bm = blockIdx.y * 128, bn = blockIdx.x * 128;

    uint32_t aoff = (uint32_t)(lane & 15) * (RSTR * 2) + ((lane >> 4) & 1) * 16;
    uint32_t boff = (uint32_t)((lane & 7) + ((lane >> 4) & 1) * 8) * (RSTR * 2)
                  + ((lane >> 3) & 1) * 16;

    int arow = tid >> 1, ach = (tid & 1) * 2;
    const __half* Ag = A + (size_t)(bm + arow) * K + ach * 8;
    const __half* Bg = Bw + (size_t)(bn + arow) * K + ach * 8;
    uint32_t adst = (uint32_t)arow * (RSTR * 2) + ach * 16;

    float acc[4][4][4];
#pragma unroll
    for (int i = 0; i < 4; i++)
#pragma unroll
        for (int j = 0; j < 4; j++)
#pragma unroll
            for (int c2 = 0; c2 < 4; c2++) acc[i][j][c2] = 0.f;

    int nkt = K >> 5;

    cp16(sA[0] + adst,      Ag);
    cp16(sA[0] + adst + 16, Ag + 8);
    cp16(sB[0] + adst,      Bg);
    cp16(sB[0] + adst + 16, Bg + 8);
    asm volatile("cp.async.commit_group;\n");

    int buf = 0;
    for (int kt = 0; kt < nkt; kt++) {
        if (kt + 1 < nkt) {
            int ko = (kt + 1) * 32;
            uint32_t da = sA[buf ^ 1], db = sB[buf ^ 1];
            cp16(da + adst,      Ag + ko);
            cp16(da + adst + 16, Ag + ko + 8);
            cp16(db + adst,      Bg + ko);
            cp16(db + adst + 16, Bg + ko + 8);
            asm volatile("cp.async.commit_group;\n");
            asm volatile("cp.async.wait_group 1;\n");
        } else {
            asm volatile("cp.async.wait_group 0;\n");
        }
        __syncthreads();

        uint32_t sa = sA[buf], sbb = sB[buf];
#pragma unroll
        for (int kk = 0; kk < 2; kk++) {
            uint32_t af[4][4], bf[2][4];
#pragma unroll
            for (int im = 0; im < 4; im++)
                ldm4(af[im], sa + (uint32_t)(wm + im * 16) * (RSTR * 2) + kk * 32 + aoff);
#pragma unroll
            for (int jn = 0; jn < 2; jn++)
                ldm4(bf[jn], sbb + (uint32_t)(wn + jn * 16) * (RSTR * 2) + kk * 32 + boff);
#pragma unroll
            for (int im = 0; im < 4; im++)
#pragma unroll
                for (int jn = 0; jn < 2; jn++) {
                    mma16816(acc[im][jn * 2],     af[im], bf[jn][0], bf[jn][1]);
                    mma16816(acc[im][jn * 2 + 1], af[im], bf[jn][2], bf[jn][3]);
                }
        }
        __syncthreads();
        buf ^= 1;
    }

    int g = lane >> 2, cc = lane & 3;
#pragma unroll
    for (int im = 0; im < 4; im++) {
        int row0 = bm + wm + im * 16 + g;
        int orow0 = row0, orow1 = row0 + 8;
        if (EPI == 4) {
            orow0 = decomp_win(row0, shiftp);
            orow1 = decomp_win(row0 + 8, shiftp);
        }
#pragma unroll
        for (int j = 0; j < 4; j++) {
            int col = bn + wn + j * 8 + cc * 2;
            float b0 = bias[col], b1 = bias[col + 1];
            float v0 = acc[im][j][0] + b0, v1 = acc[im][j][1] + b1;
            float v2 = acc[im][j][2] + b0, v3 = acc[im][j][3] + b1;
            if (EPI == 1) {
                v0 = fast_gelu(v0);
                v1 = fast_gelu(v1);
                v2 = fast_gelu(v2);
                v3 = fast_gelu(v3);
            }
            if (EPI == 2 || EPI == 4) {
                float2 r0v = *(const float2*)&res[(size_t)orow0 * N + col];
                float2 r1v = *(const float2*)&res[(size_t)orow1 * N + col];
                v0 += r0v.x; v1 += r0v.y; v2 += r1v.x; v3 += r1v.y;
            }
            if (EPI == 3) {
                v0 = fmaxf(v0, 0.f); v1 = fmaxf(v1, 0.f);
                v2 = fmaxf(v2, 0.f); v3 = fmaxf(v3, 0.f);
            }
            if (OHALF) {
                *(__half2*)&C16[(size_t)orow0 * N + col] = __floats2half2_rn(v0, v1);
                *(__half2*)&C16[(size_t)orow1 * N + col] = __floats2half2_rn(v2, v3);
            } else {
                float2 o0; o0.x = v0; o0.y = v1;
                float2 o1; o1.x = v2; o1.y = v3;
                *(float2*)&C[(size_t)orow0 * N + col] = o0;
                *(float2*)&C[(size_t)orow1 * N + col] = o1;
            }
        }
    }
}

// ---------------------------------------------------------------------------
// Depthwise 3x3x3 conv, channels-last; fp16 out
// ---------------------------------------------------------------------------
__global__ __launch_bounds__(256)
void dwconv_k(const float* __restrict__ in, const float* __restrict__ w,
              __half* __restrict__ out) {
    __shared__ float ws[256 * 27];
    int tid = threadIdx.x;
    for (int idx = tid; idx < 256 * 27; idx += 256) ws[idx] = w[idx];
    __syncthreads();
    int bx = blockIdx.x;
    int tc = bx & 3;  bx >>= 2;
    int wp = bx & 31; bx >>= 5;
    int hp = bx & 31; bx >>= 5;
    int b  = bx;
    int c  = tid;
    const float* ib = in  + (size_t)b * L * CH;
    __half*      ob = out + (size_t)b * L * CH;
#pragma unroll
    for (int tt = 0; tt < 8; tt++) {
        int t = tc * 8 + tt;
        float acc = 0.f;
#pragma unroll
        for (int dh = -1; dh <= 1; dh++) {
            int h2 = hp + dh; if (h2 < 0 || h2 > 31) continue;
#pragma unroll
            for (int dw = -1; dw <= 1; dw++) {
                int w2 = wp + dw; if (w2 < 0 || w2 > 31) continue;
#pragma unroll
                for (int dt = -1; dt <= 1; dt++) {
                    int t2 = t + dt; if (t2 < 0 || t2 > 31) continue;
                    acc += ws[c * 27 + (dh + 1) * 9 + (dw + 1) * 3 + (dt + 1)] *
                           ib[(size_t)(h2 * 1024 + w2 * 32 + t2) * CH + c];
                }
            }
        }
        ob[(size_t)(hp * 1024 + wp * 32 + t) * CH + c] = __float2half_rn(acc);
    }
}

// ---------------------------------------------------------------------------
// Launch
// ---------------------------------------------------------------------------
extern "C" void kernel_launch(void* const* d_in, const int* in_sizes, int n_in,
                              void* d_out, int out_size) {
    const float* x      = (const float*)d_in[0];
    const float* g1     = (const float*)d_in[1];
    const float* b1     = (const float*)d_in[2];
    const float* qkv_w  = (const float*)d_in[3];
    const float* qkv_b  = (const float*)d_in[4];
    const float* proj_w = (const float*)d_in[5];
    const float* proj_b = (const float*)d_in[6];
    const float* rpb    = (const float*)d_in[7];
    const float* g2     = (const float*)d_in[8];
    const float* b2     = (const float*)d_in[9];
    const float* fc1_w  = (const float*)d_in[10];
    const float* fc1_b  = (const float*)d_in[11];
    const float* fc2_w  = (const float*)d_in[12];
    const float* fc2_b  = (const float*)d_in[13];
    const float* dw_w   = (const float*)d_in[14];
    const float* pw_w   = (const float*)d_in[15];
    const float* pw_b   = (const float*)d_in[16];
    float* out = (float*)d_out;

    float *ph, *ptab;
    __half *hwin, *hqkv, *hmid, *hwts, *hpwT;
    cudaGetSymbolAddress((void**)&ph,   g_h);
    cudaGetSymbolAddress((void**)&hwin, g_win);
    cudaGetSymbolAddress((void**)&hqkv, g_qkv);
    cudaGetSymbolAddress((void**)&hmid, g_mid);
    cudaGetSymbolAddress((void**)&hwts, g_wts);
    cudaGetSymbolAddress((void**)&hpwT, g_pwT);
    cudaGetSymbolAddress((void**)&ptab, g_tab);
    float* fscratch = (float*)hqkv;   // fp32 view for pw output

    // weight prepass: [K][N] -> [N][K] fp16
    wtransH_k<<<dim3(8, 24, 4), dim3(32, 8)>>>(qkv_w,  hwts + W_QKV,  256, 768);
    wtransH_k<<<dim3(8, 8, 4),  dim3(32, 8)>>>(proj_w, hwts + W_PROJ, 256, 256);
    wtransH_k<<<dim3(8, 32, 4), dim3(32, 8)>>>(fc1_w,  hwts + W_FC1,  256, 1024);
    wtransH_k<<<dim3(32, 8, 4), dim3(32, 8)>>>(fc2_w,  hwts + W_FC2,  1024, 256);
    cvt_k<<<256, 256>>>(pw_w, hpwT, 65536);       // [co][ci] already [N][K]

    // x [b][c][p] -> h [b][p][c]
    transpose_k<<<dim3(8, 1024, 2), dim3(32, 8)>>>(x, ph, 256, 32768);

    for (int blk = 0; blk < 4; blk++) {
        int shift = (blk & 1) ? 2 : 0;
        ln_winpart_k<<<MROWS / 8, 256>>>(ph, g1 + blk * 256, b1 + blk * 256, hwin, shift);
        hgemm_k<0, 1><<<dim3(6, 512), 256, HG_SMEM>>>(
            hwin, hwts + W_QKV + (size_t)blk * 256 * 768, qkv_b + blk * 768, nullptr,
            nullptr, hqkv, MROWS, 768, 256, 0);
        attn_tab_k<<<64, 64>>>(rpb + blk * 343 * 8, ptab, shift);
        attn_k<<<TOTW * 2, 128>>>(hqkv, ptab, hwin, shift);
        // proj GEMM + fused window-reverse residual accumulate into h
        hgemm_k<4, 0><<<dim3(2, 512), 256, HG_SMEM>>>(
            hwin, hwts + W_PROJ + (size_t)blk * 256 * 256, proj_b + blk * 256, ph,
            ph, nullptr, MROWS, 256, 256, shift);
        ln_plain_k<<<MROWS / 8, 256>>>(ph, g2 + blk * 256, b2 + blk * 256, hwin);
        hgemm_k<1, 1><<<dim3(8, 512), 256, HG_SMEM>>>(
            hwin, hwts + W_FC1 + (size_t)blk * 256 * 1024, fc1_b + blk * 1024, nullptr,
            nullptr, hmid, MROWS, 1024, 256, 0);
        hgemm_k<2, 0><<<dim3(2, 512), 256, HG_SMEM>>>(
            hmid, hwts + W_FC2 + (size_t)blk * 1024 * 256, fc2_b + blk * 256, ph,
            ph, nullptr, MROWS, 256, 1024, 0);
    }

    dwconv_k<<<BATCH * 32 * 32 * 4, 256>>>(ph, dw_w, hwin);
    hgemm_k<3, 0><<<dim3(2, 512), 256, HG_SMEM>>>(
        hwin, hpwT, pw_b, nullptr, fscratch, nullptr, MROWS, 256, 256, 0);
    transpose_k<<<dim3(1024, 8, 2), dim3(32, 8)>>>(fscratch, out, 32768, 256);
}